// round 1
// baseline (speedup 1.0000x reference)
#include <cuda_runtime.h>
#include <math.h>

// Problem constants
#define Bb   2
#define Tt   2048
#define Dd   1024
#define Hh   16
#define DHd  64
#define Mrows (Bb*Tt)      // 4096
#define Gheads (Bb*Hh)     // 32
#define CHK  64
#define NCk  (Tt/CHK)      // 32
#define EPSv 1e-6f

// Scratch (device globals: allocation-free per harness rules)
__device__ float g_q[Gheads*Tt*DHd];
__device__ float g_k[Gheads*Tt*DHd];
__device__ float g_v[Gheads*Tt*DHd];
__device__ float g_attn[Mrows*Dd];
__device__ float g_state[Gheads*NCk*DHd*DHd];
__device__ float g_zsum[Gheads*NCk*DHd];

// ---------------------------------------------------------------------------
// SGEMM: C[M,N] = A[M,K] @ W[N,K]^T + bias,  M=4096, N=1024, K=1024
// mode 0: ELU+1 feature map, write to [g= b*H+h][t][dh] layout
// mode 1: plain,             write to [g][t][dh] layout
// mode 2: plain,             write row-major [M][N]
// ---------------------------------------------------------------------------
#define BMt 128
#define BNt 128
#define BKt 16

__global__ __launch_bounds__(256, 2)
void sgemm_kernel(const float* __restrict__ A,
                  const float* __restrict__ W,
                  const float* __restrict__ bias,
                  float* __restrict__ dst,
                  int mode)
{
    const int K = Dd;
    __shared__ float As[BKt][BMt];
    __shared__ float Bs[BKt][BNt];

    const int tid = threadIdx.x;
    const int m0 = blockIdx.x * BMt;
    const int n0 = blockIdx.y * BNt;
    const int tx = tid & 15, ty = tid >> 4;
    const int rm = ty * 8, rn = tx * 8;

    float acc[8][8];
    #pragma unroll
    for (int u = 0; u < 8; u++)
        #pragma unroll
        for (int v = 0; v < 8; v++) acc[u][v] = 0.f;

    // tile-load mapping: 512 float4 per 128x16 tile, 2 per thread
    const int lrow = tid >> 2;        // 0..63
    const int lc4  = (tid & 3) * 4;   // 0,4,8,12
    const float* Aptr = A + (size_t)(m0 + lrow) * K + lc4;
    const float* Wptr = W + (size_t)(n0 + lrow) * K + lc4;

    for (int k0 = 0; k0 < K; k0 += BKt) {
        float4 a0 = *(const float4*)(Aptr + k0);
        float4 a1 = *(const float4*)(Aptr + (size_t)64 * K + k0);
        float4 b0 = *(const float4*)(Wptr + k0);
        float4 b1 = *(const float4*)(Wptr + (size_t)64 * K + k0);

        __syncthreads();
        As[lc4+0][lrow] = a0.x; As[lc4+1][lrow] = a0.y;
        As[lc4+2][lrow] = a0.z; As[lc4+3][lrow] = a0.w;
        As[lc4+0][64+lrow] = a1.x; As[lc4+1][64+lrow] = a1.y;
        As[lc4+2][64+lrow] = a1.z; As[lc4+3][64+lrow] = a1.w;
        Bs[lc4+0][lrow] = b0.x; Bs[lc4+1][lrow] = b0.y;
        Bs[lc4+2][lrow] = b0.z; Bs[lc4+3][lrow] = b0.w;
        Bs[lc4+0][64+lrow] = b1.x; Bs[lc4+1][64+lrow] = b1.y;
        Bs[lc4+2][64+lrow] = b1.z; Bs[lc4+3][64+lrow] = b1.w;
        __syncthreads();

        #pragma unroll
        for (int k = 0; k < BKt; k++) {
            float ar[8], br[8];
            *(float4*)(ar)   = *(const float4*)&As[k][rm];
            *(float4*)(ar+4) = *(const float4*)&As[k][rm+4];
            *(float4*)(br)   = *(const float4*)&Bs[k][rn];
            *(float4*)(br+4) = *(const float4*)&Bs[k][rn+4];
            #pragma unroll
            for (int u = 0; u < 8; u++)
                #pragma unroll
                for (int v = 0; v < 8; v++)
                    acc[u][v] = fmaf(ar[u], br[v], acc[u][v]);
        }
    }

    float breg[8];
    #pragma unroll
    for (int v = 0; v < 8; v++) breg[v] = bias[n0 + rn + v];

    if (mode == 2) {
        #pragma unroll
        for (int u = 0; u < 8; u++) {
            float* row = dst + (size_t)(m0 + rm + u) * Dd + n0 + rn;
            #pragma unroll
            for (int v4 = 0; v4 < 8; v4 += 4) {
                float4 o;
                o.x = acc[u][v4+0] + breg[v4+0];
                o.y = acc[u][v4+1] + breg[v4+1];
                o.z = acc[u][v4+2] + breg[v4+2];
                o.w = acc[u][v4+3] + breg[v4+3];
                *(float4*)(row + v4) = o;
            }
        }
    } else {
        const int h  = (n0 + rn) >> 6;
        const int dd = (n0 + rn) & 63;
        #pragma unroll
        for (int u = 0; u < 8; u++) {
            int m = m0 + rm + u;
            int b = m >> 11;           // m / T
            int t = m & (Tt - 1);
            float* row = dst + ((size_t)(b * Hh + h) * Tt + t) * DHd + dd;
            float vals[8];
            #pragma unroll
            for (int v = 0; v < 8; v++) {
                float c = acc[u][v] + breg[v];
                if (mode == 0) c = (c > 0.f) ? (c + 1.f) : expf(c);
                vals[v] = c;
            }
            *(float4*)(row)     = make_float4(vals[0], vals[1], vals[2], vals[3]);
            *(float4*)(row + 4) = make_float4(vals[4], vals[5], vals[6], vals[7]);
        }
    }
}

// ---------------------------------------------------------------------------
// Pass 1: per-chunk local stats  KtV[d][e] = sum_i K[i][d]*V[i][e], ksum[d]
// grid (G, NC), 256 threads
// ---------------------------------------------------------------------------
__global__ __launch_bounds__(256)
void chunk_stats_kernel()
{
    __shared__ float sK[CHK * DHd];
    __shared__ float sV[CHK * DHd];
    const int g = blockIdx.x, c = blockIdx.y;
    const int tid = threadIdx.x;
    const float* Kg = g_k + ((size_t)g * Tt + c * CHK) * DHd;
    const float* Vg = g_v + ((size_t)g * Tt + c * CHK) * DHd;

    for (int i = tid; i < CHK * DHd / 4; i += 256) {
        ((float4*)sK)[i] = ((const float4*)Kg)[i];
        ((float4*)sV)[i] = ((const float4*)Vg)[i];
    }
    __syncthreads();

    const int tx = tid & 15, ty = tid >> 4;
    const int d0 = ty * 4, e0 = tx * 4;
    float acc[4][4];
    #pragma unroll
    for (int u = 0; u < 4; u++)
        #pragma unroll
        for (int v = 0; v < 4; v++) acc[u][v] = 0.f;

    for (int i = 0; i < CHK; i++) {
        float4 a = *(const float4*)&sK[i * DHd + d0];
        float4 b = *(const float4*)&sV[i * DHd + e0];
        float ar[4] = {a.x, a.y, a.z, a.w};
        float br[4] = {b.x, b.y, b.z, b.w};
        #pragma unroll
        for (int u = 0; u < 4; u++)
            #pragma unroll
            for (int v = 0; v < 4; v++)
                acc[u][v] = fmaf(ar[u], br[v], acc[u][v]);
    }

    float* outp = g_state + ((size_t)g * NCk + c) * DHd * DHd;
    #pragma unroll
    for (int u = 0; u < 4; u++)
        *(float4*)&outp[(d0 + u) * DHd + e0] =
            make_float4(acc[u][0], acc[u][1], acc[u][2], acc[u][3]);

    if (tid < DHd) {
        float s = 0.f;
        for (int i = 0; i < CHK; i++) s += sK[i * DHd + tid];
        g_zsum[((size_t)g * NCk + c) * DHd + tid] = s;
    }
}

// ---------------------------------------------------------------------------
// Pass 2: exclusive prefix over chunks
// ---------------------------------------------------------------------------
__global__ void scan_state_kernel()
{
    const int g = blockIdx.x;
    const int j = blockIdx.y * 256 + threadIdx.x;   // < 4096
    float run = 0.f;
    float* base = g_state + (size_t)g * NCk * DHd * DHd + j;
    for (int c = 0; c < NCk; c++) {
        float v = base[(size_t)c * DHd * DHd];
        base[(size_t)c * DHd * DHd] = run;
        run += v;
    }
}

__global__ void scan_z_kernel()
{
    const int g = blockIdx.x;
    const int j = threadIdx.x;  // < 64
    float run = 0.f;
    float* base = g_zsum + (size_t)g * NCk * DHd + j;
    for (int c = 0; c < NCk; c++) {
        float v = base[c * DHd];
        base[c * DHd] = run;
        run += v;
    }
}

// ---------------------------------------------------------------------------
// Pass 3: per-chunk output.  out = (maskedA@V + Q@S) / max(denom, eps)
// grid (G, NC), 256 threads, dynamic smem
// ---------------------------------------------------------------------------
__global__ __launch_bounds__(256)
void attn_out_kernel()
{
    extern __shared__ float sm[];
    float* sQ   = sm;            // 4096 (pitch 64)
    float* sKV  = sQ + 4096;     // 4160 (K pitch 65, then V pitch 64)
    float* sS   = sKV + 4160;    // 4096 (pitch 64)
    float* sA   = sS + 4096;     // 4096 (pitch 64)
    float* zrun = sA + 4096;     // 64
    float* sden = zrun + 64;     // 64

    const int g = blockIdx.x, c = blockIdx.y;
    const int tid = threadIdx.x;
    const float* Qg = g_q + ((size_t)g * Tt + c * CHK) * DHd;
    const float* Kg = g_k + ((size_t)g * Tt + c * CHK) * DHd;
    const float* Vg = g_v + ((size_t)g * Tt + c * CHK) * DHd;
    const float* Sg = g_state + ((size_t)g * NCk + c) * DHd * DHd;

    // Load Q, S (flat), K (pitch 65)
    for (int i = tid; i < 1024; i += 256) {
        ((float4*)sQ)[i] = ((const float4*)Qg)[i];
        ((float4*)sS)[i] = ((const float4*)Sg)[i];
        float4 kv = ((const float4*)Kg)[i];
        int j = i * 4;
        int r = j >> 6, col = j & 63;
        float* p = sKV + r * 65 + col;
        p[0] = kv.x; p[1] = kv.y; p[2] = kv.z; p[3] = kv.w;
    }
    if (tid < DHd) zrun[tid] = g_zsum[((size_t)g * NCk + c) * DHd + tid];
    __syncthreads();

    const int tx = tid & 15, ty = tid >> 4;
    const int i0 = ty * 4, j0 = tx * 4;

    // A = (Q K^T) masked causal (inclusive)
    {
        float acc[4][4];
        #pragma unroll
        for (int u = 0; u < 4; u++)
            #pragma unroll
            for (int v = 0; v < 4; v++) acc[u][v] = 0.f;
        for (int d = 0; d < DHd; d++) {
            float a[4], b[4];
            #pragma unroll
            for (int u = 0; u < 4; u++) a[u] = sQ[(i0 + u) * 64 + d];
            #pragma unroll
            for (int v = 0; v < 4; v++) b[v] = sKV[(j0 + v) * 65 + d];
            #pragma unroll
            for (int u = 0; u < 4; u++)
                #pragma unroll
                for (int v = 0; v < 4; v++)
                    acc[u][v] = fmaf(a[u], b[v], acc[u][v]);
        }
        #pragma unroll
        for (int u = 0; u < 4; u++)
            #pragma unroll
            for (int v = 0; v < 4; v++)
                sA[(i0 + u) * 64 + j0 + v] = (j0 + v <= i0 + u) ? acc[u][v] : 0.f;
    }
    __syncthreads();

    // Load V over K's buffer (pitch 64); denom in parallel
    for (int i = tid; i < 1024; i += 256)
        ((float4*)sKV)[i] = ((const float4*)Vg)[i];
    if (tid < CHK) {
        float s = 0.f;
        for (int j = 0; j < CHK; j++) s += sA[tid * 64 + j];
        for (int d = 0; d < DHd; d++) s = fmaf(sQ[tid * 64 + d], zrun[d], s);
        sden[tid] = fmaxf(s, EPSv);
    }
    __syncthreads();

    // num = A@V + Q@S ; out = num / denom
    {
        const int e0 = j0;
        float acc[4][4];
        #pragma unroll
        for (int u = 0; u < 4; u++)
            #pragma unroll
            for (int v = 0; v < 4; v++) acc[u][v] = 0.f;

        for (int j = 0; j < CHK; j++) {
            float4 b4 = *(const float4*)&sKV[j * 64 + e0];
            float b[4] = {b4.x, b4.y, b4.z, b4.w};
            float a[4];
            #pragma unroll
            for (int u = 0; u < 4; u++) a[u] = sA[(i0 + u) * 64 + j];
            #pragma unroll
            for (int u = 0; u < 4; u++)
                #pragma unroll
                for (int v = 0; v < 4; v++)
                    acc[u][v] = fmaf(a[u], b[v], acc[u][v]);
        }
        for (int d = 0; d < DHd; d++) {
            float4 b4 = *(const float4*)&sS[d * 64 + e0];
            float b[4] = {b4.x, b4.y, b4.z, b4.w};
            float a[4];
            #pragma unroll
            for (int u = 0; u < 4; u++) a[u] = sQ[(i0 + u) * 64 + d];
            #pragma unroll
            for (int u = 0; u < 4; u++)
                #pragma unroll
                for (int v = 0; v < 4; v++)
                    acc[u][v] = fmaf(a[u], b[v], acc[u][v]);
        }

        const int b = g / Hh, h = g % Hh;
        #pragma unroll
        for (int u = 0; u < 4; u++) {
            int t = c * CHK + i0 + u;
            float inv = 1.f / sden[i0 + u];
            float4 o = make_float4(acc[u][0] * inv, acc[u][1] * inv,
                                   acc[u][2] * inv, acc[u][3] * inv);
            *(float4*)&g_attn[((size_t)(b * Tt + t) * Hh + h) * DHd + e0] = o;
        }
    }
}

// ---------------------------------------------------------------------------
extern "C" void kernel_launch(void* const* d_in, const int* in_sizes, int n_in,
                              void* d_out, int out_size)
{
    const float* x  = (const float*)d_in[0];
    const float* Wq = (const float*)d_in[1];
    const float* bq = (const float*)d_in[2];
    const float* Wk = (const float*)d_in[3];
    const float* bk = (const float*)d_in[4];
    const float* Wv = (const float*)d_in[5];
    const float* bv = (const float*)d_in[6];
    const float* Wo = (const float*)d_in[7];
    const float* bo = (const float*)d_in[8];
    float* out = (float*)d_out;

    float *pq, *pk, *pv, *pattn;
    cudaGetSymbolAddress((void**)&pq,    g_q);
    cudaGetSymbolAddress((void**)&pk,    g_k);
    cudaGetSymbolAddress((void**)&pv,    g_v);
    cudaGetSymbolAddress((void**)&pattn, g_attn);

    const int smem3 = (4096 + 4160 + 4096 + 4096 + 64 + 64) * sizeof(float);
    cudaFuncSetAttribute(attn_out_kernel,
                         cudaFuncAttributeMaxDynamicSharedMemorySize, smem3);

    dim3 gGemm(Mrows / BMt, Dd / BNt);
    sgemm_kernel<<<gGemm, 256>>>(x, Wq, bq, pq, 0);
    sgemm_kernel<<<gGemm, 256>>>(x, Wk, bk, pk, 0);
    sgemm_kernel<<<gGemm, 256>>>(x, Wv, bv, pv, 1);

    chunk_stats_kernel<<<dim3(Gheads, NCk), 256>>>();
    scan_state_kernel<<<dim3(Gheads, DHd * DHd / 256), 256>>>();
    scan_z_kernel<<<Gheads, DHd>>>();
    attn_out_kernel<<<dim3(Gheads, NCk), 256, smem3>>>();

    sgemm_kernel<<<gGemm, 256>>>(pattn, Wo, bo, out, 2);
}

// round 3
// speedup vs baseline: 1.9167x; 1.9167x over previous
#include <cuda_runtime.h>
#include <cuda_bf16.h>
#include <cstdint>
#include <math.h>

// Problem constants
#define Bb   2
#define Tt   2048
#define Dd   1024
#define Hh   16
#define DHd  64
#define Mrows (Bb*Tt)      // 4096
#define Gheads (Bb*Hh)     // 32
#define CHK  64
#define NCk  (Tt/CHK)      // 32
#define EPSv 1e-6f

// Scratch (device globals: allocation-free per harness rules)
__device__ float g_q[Gheads*Tt*DHd];
__device__ float g_k[Gheads*Tt*DHd];
__device__ float g_v[Gheads*Tt*DHd];
__device__ float g_state[Gheads*NCk*DHd*DHd];
__device__ float g_zsum[Gheads*NCk*DHd];

// bf16 hi/lo split buffers
__device__ __align__(16) __nv_bfloat16 g_xhi[Mrows*Dd];
__device__ __align__(16) __nv_bfloat16 g_xlo[Mrows*Dd];
__device__ __align__(16) __nv_bfloat16 g_whi[4*Dd*Dd];
__device__ __align__(16) __nv_bfloat16 g_wlo[4*Dd*Dd];
__device__ __align__(16) __nv_bfloat16 g_ahi[Mrows*Dd];
__device__ __align__(16) __nv_bfloat16 g_alo[Mrows*Dd];

// ===========================================================================
// helpers
// ===========================================================================
__device__ __forceinline__ uint32_t smem_to_u32(const void* p) {
    uint32_t a;
    asm("{ .reg .u64 t; cvta.to.shared.u64 t, %1; cvt.u32.u64 %0, t; }"
        : "=r"(a) : "l"(p));
    return a;
}

__device__ __forceinline__ void cp16(uint32_t saddr, const void* g) {
    asm volatile("cp.async.cg.shared.global [%0], [%1], 16;"
                 :: "r"(saddr), "l"(g));
}
#define CP_COMMIT() asm volatile("cp.async.commit_group;" ::: "memory")
#define CP_WAIT1()  asm volatile("cp.async.wait_group 1;" ::: "memory")

#define LDSM4(r, addr) \
    asm volatile("ldmatrix.sync.aligned.m8n8.x4.shared.b16 {%0,%1,%2,%3}, [%4];" \
                 : "=r"((r)[0]), "=r"((r)[1]), "=r"((r)[2]), "=r"((r)[3]) \
                 : "r"(addr))

__device__ __forceinline__ void mma16816(float* c, const uint32_t* a, const uint32_t* b) {
    asm volatile(
        "mma.sync.aligned.m16n8k16.row.col.f32.bf16.bf16.f32 "
        "{%0,%1,%2,%3}, {%4,%5,%6,%7}, {%8,%9}, {%0,%1,%2,%3};"
        : "+f"(c[0]), "+f"(c[1]), "+f"(c[2]), "+f"(c[3])
        : "r"(a[0]), "r"(a[1]), "r"(a[2]), "r"(a[3]), "r"(b[0]), "r"(b[1]));
}

// fp32 float4 -> packed hi/lo bf16 (4 each, as uint2)
__device__ __forceinline__ void split_bf16x4(float4 a, uint2& hi, uint2& lo)
{
    __nv_bfloat16 h0 = __float2bfloat16(a.x);
    __nv_bfloat16 h1 = __float2bfloat16(a.y);
    __nv_bfloat16 h2 = __float2bfloat16(a.z);
    __nv_bfloat16 h3 = __float2bfloat16(a.w);
    __nv_bfloat16 l0 = __float2bfloat16(a.x - __bfloat162float(h0));
    __nv_bfloat16 l1 = __float2bfloat16(a.y - __bfloat162float(h1));
    __nv_bfloat16 l2 = __float2bfloat16(a.z - __bfloat162float(h2));
    __nv_bfloat16 l3 = __float2bfloat16(a.w - __bfloat162float(h3));
    hi.x = (uint32_t)__bfloat16_as_ushort(h0) | ((uint32_t)__bfloat16_as_ushort(h1) << 16);
    hi.y = (uint32_t)__bfloat16_as_ushort(h2) | ((uint32_t)__bfloat16_as_ushort(h3) << 16);
    lo.x = (uint32_t)__bfloat16_as_ushort(l0) | ((uint32_t)__bfloat16_as_ushort(l1) << 16);
    lo.y = (uint32_t)__bfloat16_as_ushort(l2) | ((uint32_t)__bfloat16_as_ushort(l3) << 16);
}

// ===========================================================================
// split: fp32 -> bf16 hi/lo
// ===========================================================================
__global__ void split_kernel(const float4* __restrict__ src,
                             uint2* __restrict__ hi, uint2* __restrict__ lo, int n4)
{
    int i = blockIdx.x * blockDim.x + threadIdx.x;
    if (i >= n4) return;
    float4 v = __ldg(&src[i]);
    uint2 h, l;
    split_bf16x4(v, h, l);
    hi[i] = h;
    lo[i] = l;
}

// ===========================================================================
// Tensor-core GEMM via mma.sync (bf16x3 split):
// C[M=4096,N=1024] = A[M,K=1024] @ W[N,K]^T + bias
// mode 0: ELU+1 -> [g][t][dh];  mode 1: plain -> [g][t][dh];  mode 2: plain [M][N]
// ===========================================================================
#define BKc   32                 // bf16 K per chunk
#define NCH   (Dd/BKc)           // 32
#define SSTR  40                 // smem row stride (bf16), pad 8
#define TILE_SMB (128*SSTR*2)    // 10240 B per tile
#define STAGE_SMB (4*TILE_SMB)   // Ah, Al, Wh, Wl = 40960 B
#define NSTAGE 3
#define SMEM_GEMM (NSTAGE*STAGE_SMB)   // 122880 B

__global__ __launch_bounds__(256, 1)
void mma_gemm_kernel(const __nv_bfloat16* __restrict__ Ahi,
                     const __nv_bfloat16* __restrict__ Alo,
                     const __nv_bfloat16* __restrict__ Whi,
                     const __nv_bfloat16* __restrict__ Wlo,
                     const float* __restrict__ bias,
                     float* __restrict__ dst, int mode)
{
    extern __shared__ char smem[];
    const uint32_t sb = smem_to_u32(smem);
    const int tid  = threadIdx.x;
    const int lane = tid & 31, wid = tid >> 5;
    const int m0 = blockIdx.x * 128, n0 = blockIdx.y * 128;

    // ---- loader mapping: 4 tiles x 64 threads, 8 x 16B chunks each ----
    const int ltile = tid >> 6;      // 0:Ahi 1:Alo 2:Whi 3:Wlo
    const int lt    = tid & 63;
    const __nv_bfloat16* gtile;
    if      (ltile == 0) gtile = Ahi + (size_t)m0 * Dd;
    else if (ltile == 1) gtile = Alo + (size_t)m0 * Dd;
    else if (ltile == 2) gtile = Whi + (size_t)n0 * Dd;
    else                 gtile = Wlo + (size_t)n0 * Dd;

    float acc[2][8][4];
    #pragma unroll
    for (int a = 0; a < 2; a++)
        #pragma unroll
        for (int b = 0; b < 8; b++)
            #pragma unroll
            for (int c = 0; c < 4; c++) acc[a][b][c] = 0.f;

    // issue loads of chunk kc into stage kc%NSTAGE
    auto issue = [&](int kc) {
        const uint32_t stb = sb + (kc % NSTAGE) * STAGE_SMB + ltile * TILE_SMB;
        const __nv_bfloat16* g = gtile + kc * BKc;
        #pragma unroll
        for (int j = 0; j < 8; j++) {
            int chunk = lt + j * 64;          // 0..511
            int row = chunk >> 2;
            int c8  = (chunk & 3) * 8;
            cp16(stb + (uint32_t)(row * SSTR + c8) * 2,
                 g + (size_t)row * Dd + c8);
        }
    };

    issue(0); CP_COMMIT();
    issue(1); CP_COMMIT();

    // fragment address offsets
    const int wm = (wid & 3) * 32;
    const int wn = (wid >> 2) * 64;
    const int arow = (lane & 7) + ((lane >> 3) & 1) * 8;
    const int acol = ((lane >> 4) & 1) * 8;
    const int brow = (lane & 7) + ((lane >> 4) & 1) * 8;
    const int bcol = ((lane >> 3) & 1) * 8;

    for (int kc = 0; kc < NCH; kc++) {
        CP_WAIT1();
        __syncthreads();
        if (kc + 2 < NCH) issue(kc + 2);
        CP_COMMIT();

        const uint32_t stb = sb + (kc % NSTAGE) * STAGE_SMB;
        const uint32_t aH = stb;
        const uint32_t aL = stb + TILE_SMB;
        const uint32_t wH = stb + 2 * TILE_SMB;
        const uint32_t wL = stb + 3 * TILE_SMB;

        #pragma unroll
        for (int ks = 0; ks < 2; ks++) {
            uint32_t ah[2][4], al[2][4];
            #pragma unroll
            for (int mi = 0; mi < 2; mi++) {
                uint32_t off = (uint32_t)((wm + mi * 16 + arow) * SSTR + ks * 16 + acol) * 2;
                LDSM4(ah[mi], aH + off);
                LDSM4(al[mi], aL + off);
            }
            uint32_t bh[4][4], bl[4][4];
            #pragma unroll
            for (int nj = 0; nj < 4; nj++) {
                uint32_t off = (uint32_t)((wn + nj * 16 + brow) * SSTR + ks * 16 + bcol) * 2;
                LDSM4(bh[nj], wH + off);
                LDSM4(bl[nj], wL + off);
            }
            #pragma unroll
            for (int mi = 0; mi < 2; mi++)
                #pragma unroll
                for (int ni = 0; ni < 8; ni++) {
                    const uint32_t* bhp = &bh[ni >> 1][(ni & 1) * 2];
                    const uint32_t* blp = &bl[ni >> 1][(ni & 1) * 2];
                    mma16816(acc[mi][ni], ah[mi], bhp);
                    mma16816(acc[mi][ni], ah[mi], blp);
                    mma16816(acc[mi][ni], al[mi], bhp);
                }
        }
        __syncthreads();
    }

    // ---- epilogue ----
    const int gid = lane >> 2, qid = lane & 3;
    float bv[16];
    #pragma unroll
    for (int ni = 0; ni < 8; ni++) {
        int n = n0 + wn + ni * 8 + qid * 2;
        bv[2 * ni]     = __ldg(&bias[n]);
        bv[2 * ni + 1] = __ldg(&bias[n + 1]);
    }

    #pragma unroll
    for (int mi = 0; mi < 2; mi++) {
        #pragma unroll
        for (int rr = 0; rr < 2; rr++) {
            const int m = m0 + wm + mi * 16 + gid + rr * 8;
            #pragma unroll
            for (int ni = 0; ni < 8; ni++) {
                const int n = n0 + wn + ni * 8 + qid * 2;
                float v0 = acc[mi][ni][rr * 2 + 0] + bv[2 * ni];
                float v1 = acc[mi][ni][rr * 2 + 1] + bv[2 * ni + 1];
                if (mode == 0) {
                    v0 = (v0 > 0.f) ? (v0 + 1.f) : expf(v0);
                    v1 = (v1 > 0.f) ? (v1 + 1.f) : expf(v1);
                }
                if (mode == 2) {
                    *(float2*)&dst[(size_t)m * Dd + n] = make_float2(v0, v1);
                } else {
                    const int h = n >> 6, dh = n & 63;
                    const int b = m >> 11, t = m & (Tt - 1);
                    *(float2*)&dst[((size_t)(b * Hh + h) * Tt + t) * DHd + dh] =
                        make_float2(v0, v1);
                }
            }
        }
    }
}

// ---------------------------------------------------------------------------
// Pass 1: per-chunk local stats  KtV[d][e] = sum_i K[i][d]*V[i][e], ksum[d]
// ---------------------------------------------------------------------------
__global__ __launch_bounds__(256)
void chunk_stats_kernel()
{
    __shared__ float sK[CHK * DHd];
    __shared__ float sV[CHK * DHd];
    const int g = blockIdx.x, c = blockIdx.y;
    const int tid = threadIdx.x;
    const float* Kg = g_k + ((size_t)g * Tt + c * CHK) * DHd;
    const float* Vg = g_v + ((size_t)g * Tt + c * CHK) * DHd;

    for (int i = tid; i < CHK * DHd / 4; i += 256) {
        ((float4*)sK)[i] = ((const float4*)Kg)[i];
        ((float4*)sV)[i] = ((const float4*)Vg)[i];
    }
    __syncthreads();

    const int tx = tid & 15, ty = tid >> 4;
    const int d0 = ty * 4, e0 = tx * 4;
    float acc[4][4];
    #pragma unroll
    for (int u = 0; u < 4; u++)
        #pragma unroll
        for (int v = 0; v < 4; v++) acc[u][v] = 0.f;

    for (int i = 0; i < CHK; i++) {
        float4 a = *(const float4*)&sK[i * DHd + d0];
        float4 b = *(const float4*)&sV[i * DHd + e0];
        float ar[4] = {a.x, a.y, a.z, a.w};
        float br[4] = {b.x, b.y, b.z, b.w};
        #pragma unroll
        for (int u = 0; u < 4; u++)
            #pragma unroll
            for (int v = 0; v < 4; v++)
                acc[u][v] = fmaf(ar[u], br[v], acc[u][v]);
    }

    float* outp = g_state + ((size_t)g * NCk + c) * DHd * DHd;
    #pragma unroll
    for (int u = 0; u < 4; u++)
        *(float4*)&outp[(d0 + u) * DHd + e0] =
            make_float4(acc[u][0], acc[u][1], acc[u][2], acc[u][3]);

    if (tid < DHd) {
        float s = 0.f;
        for (int i = 0; i < CHK; i++) s += sK[i * DHd + tid];
        g_zsum[((size_t)g * NCk + c) * DHd + tid] = s;
    }
}

// ---------------------------------------------------------------------------
// Pass 2: exclusive prefix over chunks
// ---------------------------------------------------------------------------
__global__ void scan_state_kernel()
{
    const int g = blockIdx.x;
    const int j = blockIdx.y * 256 + threadIdx.x;   // < 4096
    float run = 0.f;
    float* base = g_state + (size_t)g * NCk * DHd * DHd + j;
    for (int c = 0; c < NCk; c++) {
        float v = base[(size_t)c * DHd * DHd];
        base[(size_t)c * DHd * DHd] = run;
        run += v;
    }
}

__global__ void scan_z_kernel()
{
    const int g = blockIdx.x;
    const int j = threadIdx.x;  // < 64
    float run = 0.f;
    float* base = g_zsum + (size_t)g * NCk * DHd + j;
    for (int c = 0; c < NCk; c++) {
        float v = base[c * DHd];
        base[c * DHd] = run;
        run += v;
    }
}

// ---------------------------------------------------------------------------
// Pass 3: per-chunk output.  out = (maskedA@V + Q@S) / max(denom, eps)
// Writes bf16 hi/lo split directly (feeds final GEMM).
// ---------------------------------------------------------------------------
__global__ __launch_bounds__(256)
void attn_out_kernel()
{
    extern __shared__ float sm[];
    float* sQ   = sm;            // 4096 (pitch 64)
    float* sKV  = sQ + 4096;     // 4160 (K pitch 65, then V pitch 64)
    float* sS   = sKV + 4160;    // 4096 (pitch 64)
    float* sA   = sS + 4096;     // 4096 (pitch 64)
    float* zrun = sA + 4096;     // 64
    float* sden = zrun + 64;     // 64

    const int g = blockIdx.x, c = blockIdx.y;
    const int tid = threadIdx.x;
    const float* Qg = g_q + ((size_t)g * Tt + c * CHK) * DHd;
    const float* Kg = g_k + ((size_t)g * Tt + c * CHK) * DHd;
    const float* Vg = g_v + ((size_t)g * Tt + c * CHK) * DHd;
    const float* Sg = g_state + ((size_t)g * NCk + c) * DHd * DHd;

    for (int i = tid; i < 1024; i += 256) {
        ((float4*)sQ)[i] = ((const float4*)Qg)[i];
        ((float4*)sS)[i] = ((const float4*)Sg)[i];
        float4 kv = ((const float4*)Kg)[i];
        int j = i * 4;
        int r = j >> 6, col = j & 63;
        float* p = sKV + r * 65 + col;
        p[0] = kv.x; p[1] = kv.y; p[2] = kv.z; p[3] = kv.w;
    }
    if (tid < DHd) zrun[tid] = g_zsum[((size_t)g * NCk + c) * DHd + tid];
    __syncthreads();

    const int tx = tid & 15, ty = tid >> 4;
    const int i0 = ty * 4, j0 = tx * 4;

    // A = (Q K^T) masked causal (inclusive)
    {
        float acc[4][4];
        #pragma unroll
        for (int u = 0; u < 4; u++)
            #pragma unroll
            for (int v = 0; v < 4; v++) acc[u][v] = 0.f;
        for (int d = 0; d < DHd; d++) {
            float a[4], b[4];
            #pragma unroll
            for (int u = 0; u < 4; u++) a[u] = sQ[(i0 + u) * 64 + d];
            #pragma unroll
            for (int v = 0; v < 4; v++) b[v] = sKV[(j0 + v) * 65 + d];
            #pragma unroll
            for (int u = 0; u < 4; u++)
                #pragma unroll
                for (int v = 0; v < 4; v++)
                    acc[u][v] = fmaf(a[u], b[v], acc[u][v]);
        }
        #pragma unroll
        for (int u = 0; u < 4; u++)
            #pragma unroll
            for (int v = 0; v < 4; v++)
                sA[(i0 + u) * 64 + j0 + v] = (j0 + v <= i0 + u) ? acc[u][v] : 0.f;
    }
    __syncthreads();

    for (int i = tid; i < 1024; i += 256)
        ((float4*)sKV)[i] = ((const float4*)Vg)[i];
    if (tid < CHK) {
        float s = 0.f;
        for (int j = 0; j < CHK; j++) s += sA[tid * 64 + j];
        for (int d = 0; d < DHd; d++) s = fmaf(sQ[tid * 64 + d], zrun[d], s);
        sden[tid] = fmaxf(s, EPSv);
    }
    __syncthreads();

    {
        const int e0 = j0;
        float acc[4][4];
        #pragma unroll
        for (int u = 0; u < 4; u++)
            #pragma unroll
            for (int v = 0; v < 4; v++) acc[u][v] = 0.f;

        for (int j = 0; j < CHK; j++) {
            float4 b4 = *(const float4*)&sKV[j * 64 + e0];
            float b[4] = {b4.x, b4.y, b4.z, b4.w};
            float a[4];
            #pragma unroll
            for (int u = 0; u < 4; u++) a[u] = sA[(i0 + u) * 64 + j];
            #pragma unroll
            for (int u = 0; u < 4; u++)
                #pragma unroll
                for (int v = 0; v < 4; v++)
                    acc[u][v] = fmaf(a[u], b[v], acc[u][v]);
        }
        for (int d = 0; d < DHd; d++) {
            float4 b4 = *(const float4*)&sS[d * 64 + e0];
            float b[4] = {b4.x, b4.y, b4.z, b4.w};
            float a[4];
            #pragma unroll
            for (int u = 0; u < 4; u++) a[u] = sQ[(i0 + u) * 64 + d];
            #pragma unroll
            for (int u = 0; u < 4; u++)
                #pragma unroll
                for (int v = 0; v < 4; v++)
                    acc[u][v] = fmaf(a[u], b[v], acc[u][v]);
        }

        const int b = g / Hh, h = g % Hh;
        #pragma unroll
        for (int u = 0; u < 4; u++) {
            int t = c * CHK + i0 + u;
            float inv = 1.f / sden[i0 + u];
            float4 o = make_float4(acc[u][0] * inv, acc[u][1] * inv,
                                   acc[u][2] * inv, acc[u][3] * inv);
            size_t idx = ((size_t)(b * Tt + t) * Hh + h) * DHd + e0;
            uint2 hi, lo;
            split_bf16x4(o, hi, lo);
            *(uint2*)&g_ahi[idx] = hi;
            *(uint2*)&g_alo[idx] = lo;
        }
    }
}

// ---------------------------------------------------------------------------
extern "C" void kernel_launch(void* const* d_in, const int* in_sizes, int n_in,
                              void* d_out, int out_size)
{
    const float* x  = (const float*)d_in[0];
    const float* Wq = (const float*)d_in[1];
    const float* bq = (const float*)d_in[2];
    const float* Wk = (const float*)d_in[3];
    const float* bk = (const float*)d_in[4];
    const float* Wv = (const float*)d_in[5];
    const float* bv = (const float*)d_in[6];
    const float* Wo = (const float*)d_in[7];
    const float* bo = (const float*)d_in[8];
    float* out = (float*)d_out;

    float *pq, *pk, *pv;
    __nv_bfloat16 *pxhi, *pxlo, *pwhi, *pwlo, *pahi, *palo;
    cudaGetSymbolAddress((void**)&pq,   g_q);
    cudaGetSymbolAddress((void**)&pk,   g_k);
    cudaGetSymbolAddress((void**)&pv,   g_v);
    cudaGetSymbolAddress((void**)&pxhi, g_xhi);
    cudaGetSymbolAddress((void**)&pxlo, g_xlo);
    cudaGetSymbolAddress((void**)&pwhi, g_whi);
    cudaGetSymbolAddress((void**)&pwlo, g_wlo);
    cudaGetSymbolAddress((void**)&pahi, g_ahi);
    cudaGetSymbolAddress((void**)&palo, g_alo);

    static int attr_done = 0;
    if (!attr_done) {
        cudaFuncSetAttribute(mma_gemm_kernel,
                             cudaFuncAttributeMaxDynamicSharedMemorySize, SMEM_GEMM);
        cudaFuncSetAttribute(attn_out_kernel,
                             cudaFuncAttributeMaxDynamicSharedMemorySize,
                             (4096 + 4160 + 4096 + 4096 + 64 + 64) * (int)sizeof(float));
        attr_done = 1;
    }
    const int smem3 = (4096 + 4160 + 4096 + 4096 + 64 + 64) * sizeof(float);

    // --- split fp32 -> bf16 hi/lo ---
    const int xN4 = Mrows * Dd / 4;       // 1M
    const int wN4 = Dd * Dd / 4;          // 256K
    split_kernel<<<(xN4 + 255) / 256, 256>>>((const float4*)x,
        (uint2*)pxhi, (uint2*)pxlo, xN4);
    split_kernel<<<(wN4 + 255) / 256, 256>>>((const float4*)Wq,
        (uint2*)(pwhi + 0 * (size_t)Dd * Dd), (uint2*)(pwlo + 0 * (size_t)Dd * Dd), wN4);
    split_kernel<<<(wN4 + 255) / 256, 256>>>((const float4*)Wk,
        (uint2*)(pwhi + 1 * (size_t)Dd * Dd), (uint2*)(pwlo + 1 * (size_t)Dd * Dd), wN4);
    split_kernel<<<(wN4 + 255) / 256, 256>>>((const float4*)Wv,
        (uint2*)(pwhi + 2 * (size_t)Dd * Dd), (uint2*)(pwlo + 2 * (size_t)Dd * Dd), wN4);
    split_kernel<<<(wN4 + 255) / 256, 256>>>((const float4*)Wo,
        (uint2*)(pwhi + 3 * (size_t)Dd * Dd), (uint2*)(pwlo + 3 * (size_t)Dd * Dd), wN4);

    // --- projections (tensor cores) ---
    dim3 gGemm(Mrows / 128, Dd / 128);   // (32, 8)
    mma_gemm_kernel<<<gGemm, 256, SMEM_GEMM>>>(pxhi, pxlo,
        pwhi + 0 * (size_t)Dd * Dd, pwlo + 0 * (size_t)Dd * Dd, bq, pq, 0);
    mma_gemm_kernel<<<gGemm, 256, SMEM_GEMM>>>(pxhi, pxlo,
        pwhi + 1 * (size_t)Dd * Dd, pwlo + 1 * (size_t)Dd * Dd, bk, pk, 0);
    mma_gemm_kernel<<<gGemm, 256, SMEM_GEMM>>>(pxhi, pxlo,
        pwhi + 2 * (size_t)Dd * Dd, pwlo + 2 * (size_t)Dd * Dd, bv, pv, 1);

    // --- linear attention ---
    chunk_stats_kernel<<<dim3(Gheads, NCk), 256>>>();
    scan_state_kernel<<<dim3(Gheads, DHd * DHd / 256), 256>>>();
    scan_z_kernel<<<Gheads, DHd>>>();
    attn_out_kernel<<<dim3(Gheads, NCk), 256, smem3>>>();

    // --- output projection ---
    mma_gemm_kernel<<<gGemm, 256, SMEM_GEMM>>>(pahi, palo,
        pwhi + 3 * (size_t)Dd * Dd, pwlo + 3 * (size_t)Dd * Dd, bo, out, 2);
}

// round 4
// speedup vs baseline: 2.1970x; 1.1462x over previous
#include <cuda_runtime.h>
#include <cuda_bf16.h>
#include <cstdint>
#include <math.h>

// Problem constants
#define Bb   2
#define Tt   2048
#define Dd   1024
#define Hh   16
#define DHd  64
#define Mrows (Bb*Tt)      // 4096
#define Gheads (Bb*Hh)     // 32
#define CHK  64
#define NCk  (Tt/CHK)      // 32
#define EPSv 1e-6f

// Scratch (device globals: allocation-free per harness rules)
__device__ float g_q[Gheads*Tt*DHd];
__device__ float g_k[Gheads*Tt*DHd];
__device__ float g_v[Gheads*Tt*DHd];
__device__ float g_state[Gheads*NCk*DHd*DHd];
__device__ float g_zsum[Gheads*NCk*DHd];

// bf16 hi/lo split buffers
__device__ __align__(16) __nv_bfloat16 g_xhi[Mrows*Dd];
__device__ __align__(16) __nv_bfloat16 g_xlo[Mrows*Dd];
__device__ __align__(16) __nv_bfloat16 g_whi[4*Dd*Dd];
__device__ __align__(16) __nv_bfloat16 g_wlo[4*Dd*Dd];
__device__ __align__(16) __nv_bfloat16 g_ahi[Mrows*Dd];
__device__ __align__(16) __nv_bfloat16 g_alo[Mrows*Dd];

// ===========================================================================
// helpers
// ===========================================================================
__device__ __forceinline__ uint32_t smem_to_u32(const void* p) {
    uint32_t a;
    asm("{ .reg .u64 t; cvta.to.shared.u64 t, %1; cvt.u32.u64 %0, t; }"
        : "=r"(a) : "l"(p));
    return a;
}

__device__ __forceinline__ void cp16(uint32_t saddr, const void* g) {
    asm volatile("cp.async.cg.shared.global [%0], [%1], 16;"
                 :: "r"(saddr), "l"(g));
}
#define CP_COMMIT() asm volatile("cp.async.commit_group;" ::: "memory")
#define CP_WAIT0()  asm volatile("cp.async.wait_group 0;" ::: "memory")

#define LDSM4(r, addr) \
    asm volatile("ldmatrix.sync.aligned.m8n8.x4.shared.b16 {%0,%1,%2,%3}, [%4];" \
                 : "=r"((r)[0]), "=r"((r)[1]), "=r"((r)[2]), "=r"((r)[3]) \
                 : "r"(addr))

__device__ __forceinline__ void mma16816(float* c, const uint32_t* a, const uint32_t* b) {
    asm volatile(
        "mma.sync.aligned.m16n8k16.row.col.f32.bf16.bf16.f32 "
        "{%0,%1,%2,%3}, {%4,%5,%6,%7}, {%8,%9}, {%0,%1,%2,%3};"
        : "+f"(c[0]), "+f"(c[1]), "+f"(c[2]), "+f"(c[3])
        : "r"(a[0]), "r"(a[1]), "r"(a[2]), "r"(a[3]), "r"(b[0]), "r"(b[1]));
}

// fp32 float4 -> packed hi/lo bf16 (4 each, as uint2)
__device__ __forceinline__ void split_bf16x4(float4 a, uint2& hi, uint2& lo)
{
    __nv_bfloat16 h0 = __float2bfloat16(a.x);
    __nv_bfloat16 h1 = __float2bfloat16(a.y);
    __nv_bfloat16 h2 = __float2bfloat16(a.z);
    __nv_bfloat16 h3 = __float2bfloat16(a.w);
    __nv_bfloat16 l0 = __float2bfloat16(a.x - __bfloat162float(h0));
    __nv_bfloat16 l1 = __float2bfloat16(a.y - __bfloat162float(h1));
    __nv_bfloat16 l2 = __float2bfloat16(a.z - __bfloat162float(h2));
    __nv_bfloat16 l3 = __float2bfloat16(a.w - __bfloat162float(h3));
    hi.x = (uint32_t)__bfloat16_as_ushort(h0) | ((uint32_t)__bfloat16_as_ushort(h1) << 16);
    hi.y = (uint32_t)__bfloat16_as_ushort(h2) | ((uint32_t)__bfloat16_as_ushort(h3) << 16);
    lo.x = (uint32_t)__bfloat16_as_ushort(l0) | ((uint32_t)__bfloat16_as_ushort(l1) << 16);
    lo.y = (uint32_t)__bfloat16_as_ushort(l2) | ((uint32_t)__bfloat16_as_ushort(l3) << 16);
}

// ===========================================================================
// split kernels: fp32 -> bf16 hi/lo
// ===========================================================================
__global__ void split_x_kernel(const float4* __restrict__ src,
                               uint2* __restrict__ hi, uint2* __restrict__ lo, int n4)
{
    int i = blockIdx.x * blockDim.x + threadIdx.x;
    if (i >= n4) return;
    float4 v = __ldg(&src[i]);
    uint2 h, l;
    split_bf16x4(v, h, l);
    hi[i] = h;
    lo[i] = l;
}

// all 4 weight matrices in one launch; quarter = i >> 18 (Dd*Dd/4 = 2^18)
__global__ void split_w_kernel(const float4* __restrict__ w0,
                               const float4* __restrict__ w1,
                               const float4* __restrict__ w2,
                               const float4* __restrict__ w3,
                               uint2* __restrict__ hi, uint2* __restrict__ lo)
{
    int i = blockIdx.x * blockDim.x + threadIdx.x;
    const int quarter = i >> 18;
    const int r = i & ((1 << 18) - 1);
    const float4* src = (quarter == 0) ? w0 : (quarter == 1) ? w1
                       : (quarter == 2) ? w2 : w3;
    float4 v = __ldg(&src[r]);
    uint2 h, l;
    split_bf16x4(v, h, l);
    hi[i] = h;
    lo[i] = l;
}

// ===========================================================================
// Tensor-core GEMM via mma.sync (bf16x3 split):
// C[M=4096,N=1024] = A[M,K=1024] @ W[N,K]^T + bias
// Batched over blockIdx.z (weight/bias/dst select).
// mode 0 (qkv): z=0,1 -> ELU+1 -> [g][t][dh]; z=2 -> plain -> [g][t][dh]
// mode 2: plain row-major [M][N] (z must be 0)
// ===========================================================================
#define BKc   64                 // bf16 K per chunk
#define NCH   (Dd/BKc)           // 16
#define SSTR  72                 // smem row stride (bf16), pad 8
#define TILE_SMB (128*SSTR*2)    // 18432 B per tile
#define STAGE_SMB (4*TILE_SMB)   // Ah, Al, Wh, Wl = 73728 B
#define SMEM_GEMM (2*STAGE_SMB)  // 147456 B

__global__ __launch_bounds__(256, 1)
void mma_gemm_kernel(const __nv_bfloat16* __restrict__ Ahi,
                     const __nv_bfloat16* __restrict__ Alo,
                     const __nv_bfloat16* __restrict__ WhiB,
                     const __nv_bfloat16* __restrict__ WloB,
                     const float* __restrict__ b0,
                     const float* __restrict__ b1,
                     const float* __restrict__ b2,
                     float* __restrict__ d0,
                     float* __restrict__ d1,
                     float* __restrict__ d2,
                     int mode)
{
    extern __shared__ char smem[];
    const uint32_t sb = smem_to_u32(smem);
    const int tid  = threadIdx.x;
    const int lane = tid & 31, wid = tid >> 5;
    const int m0 = blockIdx.x * 128, n0 = blockIdx.y * 128;
    const int z  = blockIdx.z;

    const __nv_bfloat16* Whi = WhiB + (size_t)z * Dd * Dd;
    const __nv_bfloat16* Wlo = WloB + (size_t)z * Dd * Dd;
    const float* bias = (z == 0) ? b0 : (z == 1) ? b1 : b2;
    float* dst        = (z == 0) ? d0 : (z == 1) ? d1 : d2;
    const bool do_elu = (mode == 0) && (z < 2);

    // ---- loader mapping: 4 tiles x 64 threads, 16 x 16B chunks each ----
    const int ltile = tid >> 6;      // 0:Ahi 1:Alo 2:Whi 3:Wlo
    const int lt    = tid & 63;
    const __nv_bfloat16* gtile;
    if      (ltile == 0) gtile = Ahi + (size_t)m0 * Dd;
    else if (ltile == 1) gtile = Alo + (size_t)m0 * Dd;
    else if (ltile == 2) gtile = Whi + (size_t)n0 * Dd;
    else                 gtile = Wlo + (size_t)n0 * Dd;

    float acc[2][8][4];
    #pragma unroll
    for (int a = 0; a < 2; a++)
        #pragma unroll
        for (int b = 0; b < 8; b++)
            #pragma unroll
            for (int c = 0; c < 4; c++) acc[a][b][c] = 0.f;

    // issue loads of chunk kc into stage kc&1 (128 rows x 64 bf16 per tile)
    auto issue = [&](int kc) {
        const uint32_t stb = sb + (kc & 1) * STAGE_SMB + ltile * TILE_SMB;
        const __nv_bfloat16* g = gtile + kc * BKc;
        #pragma unroll
        for (int j = 0; j < 16; j++) {
            int chunk = lt + j * 64;          // 0..1023
            int row = chunk >> 3;
            int c8  = (chunk & 7) * 8;
            cp16(stb + (uint32_t)(row * SSTR + c8) * 2,
                 g + (size_t)row * Dd + c8);
        }
    };

    issue(0); CP_COMMIT();

    // fragment address offsets
    const int wm = (wid & 3) * 32;
    const int wn = (wid >> 2) * 64;
    const int arow = (lane & 7) + ((lane >> 3) & 1) * 8;
    const int acol = ((lane >> 4) & 1) * 8;
    const int brow = (lane & 7) + ((lane >> 4) & 1) * 8;
    const int bcol = ((lane >> 3) & 1) * 8;

    for (int kc = 0; kc < NCH; kc++) {
        CP_WAIT0();
        __syncthreads();
        // after barrier: all warps finished reading stage (kc-1)&1 = (kc+1)&1
        if (kc + 1 < NCH) { issue(kc + 1); CP_COMMIT(); }

        const uint32_t stb = sb + (kc & 1) * STAGE_SMB;
        const uint32_t aH = stb;
        const uint32_t aL = stb + TILE_SMB;
        const uint32_t wH = stb + 2 * TILE_SMB;
        const uint32_t wL = stb + 3 * TILE_SMB;

        #pragma unroll
        for (int ks = 0; ks < 4; ks++) {
            uint32_t ah[2][4], al[2][4];
            #pragma unroll
            for (int mi = 0; mi < 2; mi++) {
                uint32_t off = (uint32_t)((wm + mi * 16 + arow) * SSTR + ks * 16 + acol) * 2;
                LDSM4(ah[mi], aH + off);
                LDSM4(al[mi], aL + off);
            }
            uint32_t bh[4][4], bl[4][4];
            #pragma unroll
            for (int nj = 0; nj < 4; nj++) {
                uint32_t off = (uint32_t)((wn + nj * 16 + brow) * SSTR + ks * 16 + bcol) * 2;
                LDSM4(bh[nj], wH + off);
                LDSM4(bl[nj], wL + off);
            }
            #pragma unroll
            for (int mi = 0; mi < 2; mi++)
                #pragma unroll
                for (int ni = 0; ni < 8; ni++) {
                    const uint32_t* bhp = &bh[ni >> 1][(ni & 1) * 2];
                    const uint32_t* blp = &bl[ni >> 1][(ni & 1) * 2];
                    mma16816(acc[mi][ni], ah[mi], bhp);
                    mma16816(acc[mi][ni], ah[mi], blp);
                    mma16816(acc[mi][ni], al[mi], bhp);
                }
        }
    }

    // ---- epilogue ----
    const int gid = lane >> 2, qid = lane & 3;
    float bv[16];
    #pragma unroll
    for (int ni = 0; ni < 8; ni++) {
        int n = n0 + wn + ni * 8 + qid * 2;
        bv[2 * ni]     = __ldg(&bias[n]);
        bv[2 * ni + 1] = __ldg(&bias[n + 1]);
    }

    #pragma unroll
    for (int mi = 0; mi < 2; mi++) {
        #pragma unroll
        for (int rr = 0; rr < 2; rr++) {
            const int m = m0 + wm + mi * 16 + gid + rr * 8;
            #pragma unroll
            for (int ni = 0; ni < 8; ni++) {
                const int n = n0 + wn + ni * 8 + qid * 2;
                float v0 = acc[mi][ni][rr * 2 + 0] + bv[2 * ni];
                float v1 = acc[mi][ni][rr * 2 + 1] + bv[2 * ni + 1];
                if (do_elu) {
                    v0 = (v0 > 0.f) ? (v0 + 1.f) : expf(v0);
                    v1 = (v1 > 0.f) ? (v1 + 1.f) : expf(v1);
                }
                if (mode == 2) {
                    *(float2*)&dst[(size_t)m * Dd + n] = make_float2(v0, v1);
                } else {
                    const int h = n >> 6, dh = n & 63;
                    const int b = m >> 11, t = m & (Tt - 1);
                    *(float2*)&dst[((size_t)(b * Hh + h) * Tt + t) * DHd + dh] =
                        make_float2(v0, v1);
                }
            }
        }
    }
}

// ---------------------------------------------------------------------------
// Pass 1: per-chunk local stats  KtV[d][e] = sum_i K[i][d]*V[i][e], ksum[d]
// ---------------------------------------------------------------------------
__global__ __launch_bounds__(256)
void chunk_stats_kernel()
{
    __shared__ float sK[CHK * DHd];
    __shared__ float sV[CHK * DHd];
    const int g = blockIdx.x, c = blockIdx.y;
    const int tid = threadIdx.x;
    const float* Kg = g_k + ((size_t)g * Tt + c * CHK) * DHd;
    const float* Vg = g_v + ((size_t)g * Tt + c * CHK) * DHd;

    for (int i = tid; i < CHK * DHd / 4; i += 256) {
        ((float4*)sK)[i] = ((const float4*)Kg)[i];
        ((float4*)sV)[i] = ((const float4*)Vg)[i];
    }
    __syncthreads();

    const int tx = tid & 15, ty = tid >> 4;
    const int d0 = ty * 4, e0 = tx * 4;
    float acc[4][4];
    #pragma unroll
    for (int u = 0; u < 4; u++)
        #pragma unroll
        for (int v = 0; v < 4; v++) acc[u][v] = 0.f;

    for (int i = 0; i < CHK; i++) {
        float4 a = *(const float4*)&sK[i * DHd + d0];
        float4 b = *(const float4*)&sV[i * DHd + e0];
        float ar[4] = {a.x, a.y, a.z, a.w};
        float br[4] = {b.x, b.y, b.z, b.w};
        #pragma unroll
        for (int u = 0; u < 4; u++)
            #pragma unroll
            for (int v = 0; v < 4; v++)
                acc[u][v] = fmaf(ar[u], br[v], acc[u][v]);
    }

    float* outp = g_state + ((size_t)g * NCk + c) * DHd * DHd;
    #pragma unroll
    for (int u = 0; u < 4; u++)
        *(float4*)&outp[(d0 + u) * DHd + e0] =
            make_float4(acc[u][0], acc[u][1], acc[u][2], acc[u][3]);

    if (tid < DHd) {
        float s = 0.f;
        for (int i = 0; i < CHK; i++) s += sK[i * DHd + tid];
        g_zsum[((size_t)g * NCk + c) * DHd + tid] = s;
    }
}

// ---------------------------------------------------------------------------
// Pass 2: exclusive prefix over chunks (batched loads -> register scan)
// ---------------------------------------------------------------------------
__global__ void scan_state_kernel()
{
    const int g = blockIdx.x;
    const int j = blockIdx.y * 256 + threadIdx.x;   // < 4096
    float* base = g_state + (size_t)g * NCk * DHd * DHd + j;
    float r[NCk];
    #pragma unroll
    for (int c = 0; c < NCk; c++) r[c] = base[(size_t)c * DHd * DHd];
    float run = 0.f;
    #pragma unroll
    for (int c = 0; c < NCk; c++) {
        base[(size_t)c * DHd * DHd] = run;
        run += r[c];
    }
}

__global__ void scan_z_kernel()
{
    const int g = blockIdx.x;
    const int j = threadIdx.x;  // < 64
    float* base = g_zsum + (size_t)g * NCk * DHd + j;
    float r[NCk];
    #pragma unroll
    for (int c = 0; c < NCk; c++) r[c] = base[c * DHd];
    float run = 0.f;
    #pragma unroll
    for (int c = 0; c < NCk; c++) {
        base[c * DHd] = run;
        run += r[c];
    }
}

// ---------------------------------------------------------------------------
// Pass 3: per-chunk output.  out = (maskedA@V + Q@S) / max(denom, eps)
// Writes bf16 hi/lo split directly (feeds final GEMM).
// ---------------------------------------------------------------------------
__global__ __launch_bounds__(256)
void attn_out_kernel()
{
    extern __shared__ float sm[];
    float* sQ   = sm;            // 4096 (pitch 64)
    float* sKV  = sQ + 4096;     // 4160 (K pitch 65, then V pitch 64)
    float* sS   = sKV + 4160;    // 4096 (pitch 64)
    float* sA   = sS + 4096;     // 4096 (pitch 64)
    float* zrun = sA + 4096;     // 64
    float* sden = zrun + 64;     // 64

    const int g = blockIdx.x, c = blockIdx.y;
    const int tid = threadIdx.x;
    const float* Qg = g_q + ((size_t)g * Tt + c * CHK) * DHd;
    const float* Kg = g_k + ((size_t)g * Tt + c * CHK) * DHd;
    const float* Vg = g_v + ((size_t)g * Tt + c * CHK) * DHd;
    const float* Sg = g_state + ((size_t)g * NCk + c) * DHd * DHd;

    for (int i = tid; i < 1024; i += 256) {
        ((float4*)sQ)[i] = ((const float4*)Qg)[i];
        ((float4*)sS)[i] = ((const float4*)Sg)[i];
        float4 kv = ((const float4*)Kg)[i];
        int j = i * 4;
        int r = j >> 6, col = j & 63;
        float* p = sKV + r * 65 + col;
        p[0] = kv.x; p[1] = kv.y; p[2] = kv.z; p[3] = kv.w;
    }
    if (tid < DHd) zrun[tid] = g_zsum[((size_t)g * NCk + c) * DHd + tid];
    __syncthreads();

    const int tx = tid & 15, ty = tid >> 4;
    const int i0 = ty * 4, j0 = tx * 4;

    // A = (Q K^T) masked causal (inclusive)
    {
        float acc[4][4];
        #pragma unroll
        for (int u = 0; u < 4; u++)
            #pragma unroll
            for (int v = 0; v < 4; v++) acc[u][v] = 0.f;
        for (int d = 0; d < DHd; d++) {
            float a[4], b[4];
            #pragma unroll
            for (int u = 0; u < 4; u++) a[u] = sQ[(i0 + u) * 64 + d];
            #pragma unroll
            for (int v = 0; v < 4; v++) b[v] = sKV[(j0 + v) * 65 + d];
            #pragma unroll
            for (int u = 0; u < 4; u++)
                #pragma unroll
                for (int v = 0; v < 4; v++)
                    acc[u][v] = fmaf(a[u], b[v], acc[u][v]);
        }
        #pragma unroll
        for (int u = 0; u < 4; u++)
            #pragma unroll
            for (int v = 0; v < 4; v++)
                sA[(i0 + u) * 64 + j0 + v] = (j0 + v <= i0 + u) ? acc[u][v] : 0.f;
    }
    __syncthreads();

    for (int i = tid; i < 1024; i += 256)
        ((float4*)sKV)[i] = ((const float4*)Vg)[i];
    if (tid < CHK) {
        float s = 0.f;
        for (int j = 0; j < CHK; j++) s += sA[tid * 64 + j];
        for (int d = 0; d < DHd; d++) s = fmaf(sQ[tid * 64 + d], zrun[d], s);
        sden[tid] = fmaxf(s, EPSv);
    }
    __syncthreads();

    {
        const int e0 = j0;
        float acc[4][4];
        #pragma unroll
        for (int u = 0; u < 4; u++)
            #pragma unroll
            for (int v = 0; v < 4; v++) acc[u][v] = 0.f;

        for (int j = 0; j < CHK; j++) {
            float4 b4 = *(const float4*)&sKV[j * 64 + e0];
            float b[4] = {b4.x, b4.y, b4.z, b4.w};
            float a[4];
            #pragma unroll
            for (int u = 0; u < 4; u++) a[u] = sA[(i0 + u) * 64 + j];
            #pragma unroll
            for (int u = 0; u < 4; u++)
                #pragma unroll
                for (int v = 0; v < 4; v++)
                    acc[u][v] = fmaf(a[u], b[v], acc[u][v]);
        }
        for (int d = 0; d < DHd; d++) {
            float4 b4 = *(const float4*)&sS[d * 64 + e0];
            float b[4] = {b4.x, b4.y, b4.z, b4.w};
            float a[4];
            #pragma unroll
            for (int u = 0; u < 4; u++) a[u] = sQ[(i0 + u) * 64 + d];
            #pragma unroll
            for (int u = 0; u < 4; u++)
                #pragma unroll
                for (int v = 0; v < 4; v++)
                    acc[u][v] = fmaf(a[u], b[v], acc[u][v]);
        }

        const int b = g / Hh, h = g % Hh;
        #pragma unroll
        for (int u = 0; u < 4; u++) {
            int t = c * CHK + i0 + u;
            float inv = 1.f / sden[i0 + u];
            float4 o = make_float4(acc[u][0] * inv, acc[u][1] * inv,
                                   acc[u][2] * inv, acc[u][3] * inv);
            size_t idx = ((size_t)(b * Tt + t) * Hh + h) * DHd + e0;
            uint2 hi, lo;
            split_bf16x4(o, hi, lo);
            *(uint2*)&g_ahi[idx] = hi;
            *(uint2*)&g_alo[idx] = lo;
        }
    }
}

// ---------------------------------------------------------------------------
extern "C" void kernel_launch(void* const* d_in, const int* in_sizes, int n_in,
                              void* d_out, int out_size)
{
    const float* x  = (const float*)d_in[0];
    const float* Wq = (const float*)d_in[1];
    const float* bq = (const float*)d_in[2];
    const float* Wk = (const float*)d_in[3];
    const float* bk = (const float*)d_in[4];
    const float* Wv = (const float*)d_in[5];
    const float* bv = (const float*)d_in[6];
    const float* Wo = (const float*)d_in[7];
    const float* bo = (const float*)d_in[8];
    float* out = (float*)d_out;

    float *pq, *pk, *pv;
    __nv_bfloat16 *pxhi, *pxlo, *pwhi, *pwlo, *pahi, *palo;
    cudaGetSymbolAddress((void**)&pq,   g_q);
    cudaGetSymbolAddress((void**)&pk,   g_k);
    cudaGetSymbolAddress((void**)&pv,   g_v);
    cudaGetSymbolAddress((void**)&pxhi, g_xhi);
    cudaGetSymbolAddress((void**)&pxlo, g_xlo);
    cudaGetSymbolAddress((void**)&pwhi, g_whi);
    cudaGetSymbolAddress((void**)&pwlo, g_wlo);
    cudaGetSymbolAddress((void**)&pahi, g_ahi);
    cudaGetSymbolAddress((void**)&palo, g_alo);

    static int attr_done = 0;
    if (!attr_done) {
        cudaFuncSetAttribute(mma_gemm_kernel,
                             cudaFuncAttributeMaxDynamicSharedMemorySize, SMEM_GEMM);
        cudaFuncSetAttribute(attn_out_kernel,
                             cudaFuncAttributeMaxDynamicSharedMemorySize,
                             (4096 + 4160 + 4096 + 4096 + 64 + 64) * (int)sizeof(float));
        attr_done = 1;
    }
    const int smem3 = (4096 + 4160 + 4096 + 4096 + 64 + 64) * sizeof(float);

    // --- split fp32 -> bf16 hi/lo ---
    const int xN4 = Mrows * Dd / 4;       // 1M
    const int wN4 = Dd * Dd / 4;          // 256K per matrix
    split_x_kernel<<<(xN4 + 255) / 256, 256>>>((const float4*)x,
        (uint2*)pxhi, (uint2*)pxlo, xN4);
    split_w_kernel<<<(4 * wN4) / 256, 256>>>(
        (const float4*)Wq, (const float4*)Wk, (const float4*)Wv, (const float4*)Wo,
        (uint2*)pwhi, (uint2*)pwlo);

    // --- Q/K/V projections in one batched launch (tensor cores) ---
    dim3 gQKV(Mrows / 128, Dd / 128, 3);   // (32, 8, 3)
    mma_gemm_kernel<<<gQKV, 256, SMEM_GEMM>>>(pxhi, pxlo, pwhi, pwlo,
        bq, bk, bv, pq, pk, pv, 0);

    // --- linear attention ---
    chunk_stats_kernel<<<dim3(Gheads, NCk), 256>>>();
    scan_state_kernel<<<dim3(Gheads, DHd * DHd / 256), 256>>>();
    scan_z_kernel<<<Gheads, DHd>>>();
    attn_out_kernel<<<dim3(Gheads, NCk), 256, smem3>>>();

    // --- output projection ---
    dim3 gOut(Mrows / 128, Dd / 128, 1);
    mma_gemm_kernel<<<gOut, 256, SMEM_GEMM>>>(pahi, palo,
        pwhi + 3 * (size_t)Dd * Dd, pwlo + 3 * (size_t)Dd * Dd,
        bo, bo, bo, out, out, out, 2);
}

// round 5
// speedup vs baseline: 2.2069x; 1.0045x over previous
#include <cuda_runtime.h>
#include <cuda_bf16.h>
#include <cstdint>
#include <math.h>

// Problem constants
#define Bb   2
#define Tt   2048
#define Dd   1024
#define Hh   16
#define DHd  64
#define Mrows (Bb*Tt)      // 4096
#define Gheads (Bb*Hh)     // 32
#define CHK  64
#define NCk  (Tt/CHK)      // 32
#define EPSv 1e-6f

// Scratch (device globals: allocation-free per harness rules)
__device__ float g_q[Gheads*Tt*DHd];
__device__ float g_k[Gheads*Tt*DHd];
__device__ float g_v[Gheads*Tt*DHd];
__device__ float g_state[Gheads*NCk*DHd*DHd];
__device__ float g_zsum[Gheads*NCk*DHd];

// bf16 hi/lo split buffers
__device__ __align__(16) __nv_bfloat16 g_xhi[Mrows*Dd];
__device__ __align__(16) __nv_bfloat16 g_xlo[Mrows*Dd];
__device__ __align__(16) __nv_bfloat16 g_whi[4*Dd*Dd];
__device__ __align__(16) __nv_bfloat16 g_wlo[4*Dd*Dd];
__device__ __align__(16) __nv_bfloat16 g_ahi[Mrows*Dd];
__device__ __align__(16) __nv_bfloat16 g_alo[Mrows*Dd];

// ===========================================================================
// helpers
// ===========================================================================
__device__ __forceinline__ uint32_t smem_to_u32(const void* p) {
    uint32_t a;
    asm("{ .reg .u64 t; cvta.to.shared.u64 t, %1; cvt.u32.u64 %0, t; }"
        : "=r"(a) : "l"(p));
    return a;
}

__device__ __forceinline__ void cp16(uint32_t saddr, const void* g) {
    asm volatile("cp.async.cg.shared.global [%0], [%1], 16;"
                 :: "r"(saddr), "l"(g));
}
#define CP_COMMIT() asm volatile("cp.async.commit_group;" ::: "memory")
#define CP_WAIT1()  asm volatile("cp.async.wait_group 1;" ::: "memory")

#define LDSM4(r, addr) \
    asm volatile("ldmatrix.sync.aligned.m8n8.x4.shared.b16 {%0,%1,%2,%3}, [%4];" \
                 : "=r"((r)[0]), "=r"((r)[1]), "=r"((r)[2]), "=r"((r)[3]) \
                 : "r"(addr))

__device__ __forceinline__ void mma16816(float* c, const uint32_t* a, const uint32_t* b) {
    asm volatile(
        "mma.sync.aligned.m16n8k16.row.col.f32.bf16.bf16.f32 "
        "{%0,%1,%2,%3}, {%4,%5,%6,%7}, {%8,%9}, {%0,%1,%2,%3};"
        : "+f"(c[0]), "+f"(c[1]), "+f"(c[2]), "+f"(c[3])
        : "r"(a[0]), "r"(a[1]), "r"(a[2]), "r"(a[3]), "r"(b[0]), "r"(b[1]));
}

// fp32 float4 -> packed hi/lo bf16 (4 each, as uint2)
__device__ __forceinline__ void split_bf16x4(float4 a, uint2& hi, uint2& lo)
{
    __nv_bfloat16 h0 = __float2bfloat16(a.x);
    __nv_bfloat16 h1 = __float2bfloat16(a.y);
    __nv_bfloat16 h2 = __float2bfloat16(a.z);
    __nv_bfloat16 h3 = __float2bfloat16(a.w);
    __nv_bfloat16 l0 = __float2bfloat16(a.x - __bfloat162float(h0));
    __nv_bfloat16 l1 = __float2bfloat16(a.y - __bfloat162float(h1));
    __nv_bfloat16 l2 = __float2bfloat16(a.z - __bfloat162float(h2));
    __nv_bfloat16 l3 = __float2bfloat16(a.w - __bfloat162float(h3));
    hi.x = (uint32_t)__bfloat16_as_ushort(h0) | ((uint32_t)__bfloat16_as_ushort(h1) << 16);
    hi.y = (uint32_t)__bfloat16_as_ushort(h2) | ((uint32_t)__bfloat16_as_ushort(h3) << 16);
    lo.x = (uint32_t)__bfloat16_as_ushort(l0) | ((uint32_t)__bfloat16_as_ushort(l1) << 16);
    lo.y = (uint32_t)__bfloat16_as_ushort(l2) | ((uint32_t)__bfloat16_as_ushort(l3) << 16);
}

// ===========================================================================
// split kernels: fp32 -> bf16 hi/lo
// ===========================================================================
__global__ void split_x_kernel(const float4* __restrict__ src,
                               uint2* __restrict__ hi, uint2* __restrict__ lo, int n4)
{
    int i = blockIdx.x * blockDim.x + threadIdx.x;
    if (i >= n4) return;
    float4 v = __ldg(&src[i]);
    uint2 h, l;
    split_bf16x4(v, h, l);
    hi[i] = h;
    lo[i] = l;
}

// all 4 weight matrices in one launch; quarter = i >> 18 (Dd*Dd/4 = 2^18)
__global__ void split_w_kernel(const float4* __restrict__ w0,
                               const float4* __restrict__ w1,
                               const float4* __restrict__ w2,
                               const float4* __restrict__ w3,
                               uint2* __restrict__ hi, uint2* __restrict__ lo)
{
    int i = blockIdx.x * blockDim.x + threadIdx.x;
    const int quarter = i >> 18;
    const int r = i & ((1 << 18) - 1);
    const float4* src = (quarter == 0) ? w0 : (quarter == 1) ? w1
                       : (quarter == 2) ? w2 : w3;
    float4 v = __ldg(&src[r]);
    uint2 h, l;
    split_bf16x4(v, h, l);
    hi[i] = h;
    lo[i] = l;
}

// ===========================================================================
// Tensor-core GEMM via mma.sync (bf16x3 split):
// C[M=4096,N=1024] = A[M,K=1024] @ W[N,K]^T + bias
// Batched over blockIdx.z (weight/bias/dst select).
// mode 0 (qkv): z=0,1 -> ELU+1 -> [g][t][dh]; z=2 -> plain -> [g][t][dh]
// mode 2: plain row-major [M][N] (z must be 0)
// 3-stage cp.async pipeline, one barrier per K-chunk.
// ===========================================================================
#define BKc   64                 // bf16 K per chunk
#define NCH   (Dd/BKc)           // 16
#define SSTR  72                 // smem row stride (bf16), pad 8
#define TILE_SMB (128*SSTR*2)    // 18432 B per tile
#define STAGE_SMB (4*TILE_SMB)   // Ah, Al, Wh, Wl = 73728 B
#define NSTAGE 3
#define SMEM_GEMM (NSTAGE*STAGE_SMB)  // 221184 B

__global__ __launch_bounds__(256, 1)
void mma_gemm_kernel(const __nv_bfloat16* __restrict__ Ahi,
                     const __nv_bfloat16* __restrict__ Alo,
                     const __nv_bfloat16* __restrict__ WhiB,
                     const __nv_bfloat16* __restrict__ WloB,
                     const float* __restrict__ b0,
                     const float* __restrict__ b1,
                     const float* __restrict__ b2,
                     float* __restrict__ d0,
                     float* __restrict__ d1,
                     float* __restrict__ d2,
                     int mode)
{
    extern __shared__ char smem[];
    const uint32_t sb = smem_to_u32(smem);
    const int tid  = threadIdx.x;
    const int lane = tid & 31, wid = tid >> 5;
    const int m0 = blockIdx.x * 128, n0 = blockIdx.y * 128;
    const int z  = blockIdx.z;

    const __nv_bfloat16* Whi = WhiB + (size_t)z * Dd * Dd;
    const __nv_bfloat16* Wlo = WloB + (size_t)z * Dd * Dd;
    const float* bias = (z == 0) ? b0 : (z == 1) ? b1 : b2;
    float* dst        = (z == 0) ? d0 : (z == 1) ? d1 : d2;
    const bool do_elu = (mode == 0) && (z < 2);

    // ---- loader mapping: 4 tiles x 64 threads, 16 x 16B chunks each ----
    const int ltile = tid >> 6;      // 0:Ahi 1:Alo 2:Whi 3:Wlo
    const int lt    = tid & 63;
    const __nv_bfloat16* gtile;
    if      (ltile == 0) gtile = Ahi + (size_t)m0 * Dd;
    else if (ltile == 1) gtile = Alo + (size_t)m0 * Dd;
    else if (ltile == 2) gtile = Whi + (size_t)n0 * Dd;
    else                 gtile = Wlo + (size_t)n0 * Dd;

    float acc[2][8][4];
    #pragma unroll
    for (int a = 0; a < 2; a++)
        #pragma unroll
        for (int b = 0; b < 8; b++)
            #pragma unroll
            for (int c = 0; c < 4; c++) acc[a][b][c] = 0.f;

    // issue loads of chunk kc into stage kc%NSTAGE (128 rows x 64 bf16 per tile)
    auto issue = [&](int kc) {
        const uint32_t stb = sb + (kc % NSTAGE) * STAGE_SMB + ltile * TILE_SMB;
        const __nv_bfloat16* g = gtile + kc * BKc;
        #pragma unroll
        for (int j = 0; j < 16; j++) {
            int chunk = lt + j * 64;          // 0..1023
            int row = chunk >> 3;
            int c8  = (chunk & 7) * 8;
            cp16(stb + (uint32_t)(row * SSTR + c8) * 2,
                 g + (size_t)row * Dd + c8);
        }
    };

    issue(0); CP_COMMIT();
    issue(1); CP_COMMIT();

    // fragment address offsets
    const int wm = (wid & 3) * 32;
    const int wn = (wid >> 2) * 64;
    const int arow = (lane & 7) + ((lane >> 3) & 1) * 8;
    const int acol = ((lane >> 4) & 1) * 8;
    const int brow = (lane & 7) + ((lane >> 4) & 1) * 8;
    const int bcol = ((lane >> 3) & 1) * 8;

    for (int kc = 0; kc < NCH; kc++) {
        CP_WAIT1();                    // chunk kc's loads complete; kc+1 may fly
        __syncthreads();
        // stage (kc+2)%3's previous readers finished at iter kc-1 (pre-barrier)
        if (kc + 2 < NCH) { issue(kc + 2); CP_COMMIT(); }

        const uint32_t stb = sb + (kc % NSTAGE) * STAGE_SMB;
        const uint32_t aH = stb;
        const uint32_t aL = stb + TILE_SMB;
        const uint32_t wH = stb + 2 * TILE_SMB;
        const uint32_t wL = stb + 3 * TILE_SMB;

        #pragma unroll
        for (int ks = 0; ks < 4; ks++) {
            uint32_t ah[2][4], al[2][4];
            #pragma unroll
            for (int mi = 0; mi < 2; mi++) {
                uint32_t off = (uint32_t)((wm + mi * 16 + arow) * SSTR + ks * 16 + acol) * 2;
                LDSM4(ah[mi], aH + off);
                LDSM4(al[mi], aL + off);
            }
            uint32_t bh[4][4], bl[4][4];
            #pragma unroll
            for (int nj = 0; nj < 4; nj++) {
                uint32_t off = (uint32_t)((wn + nj * 16 + brow) * SSTR + ks * 16 + bcol) * 2;
                LDSM4(bh[nj], wH + off);
                LDSM4(bl[nj], wL + off);
            }
            #pragma unroll
            for (int mi = 0; mi < 2; mi++)
                #pragma unroll
                for (int ni = 0; ni < 8; ni++) {
                    const uint32_t* bhp = &bh[ni >> 1][(ni & 1) * 2];
                    const uint32_t* blp = &bl[ni >> 1][(ni & 1) * 2];
                    mma16816(acc[mi][ni], ah[mi], bhp);
                    mma16816(acc[mi][ni], ah[mi], blp);
                    mma16816(acc[mi][ni], al[mi], bhp);
                }
        }
    }

    // ---- epilogue ----
    const int gid = lane >> 2, qid = lane & 3;
    float bv[16];
    #pragma unroll
    for (int ni = 0; ni < 8; ni++) {
        int n = n0 + wn + ni * 8 + qid * 2;
        bv[2 * ni]     = __ldg(&bias[n]);
        bv[2 * ni + 1] = __ldg(&bias[n + 1]);
    }

    #pragma unroll
    for (int mi = 0; mi < 2; mi++) {
        #pragma unroll
        for (int rr = 0; rr < 2; rr++) {
            const int m = m0 + wm + mi * 16 + gid + rr * 8;
            #pragma unroll
            for (int ni = 0; ni < 8; ni++) {
                const int n = n0 + wn + ni * 8 + qid * 2;
                float v0 = acc[mi][ni][rr * 2 + 0] + bv[2 * ni];
                float v1 = acc[mi][ni][rr * 2 + 1] + bv[2 * ni + 1];
                if (do_elu) {
                    v0 = (v0 > 0.f) ? (v0 + 1.f) : expf(v0);
                    v1 = (v1 > 0.f) ? (v1 + 1.f) : expf(v1);
                }
                if (mode == 2) {
                    *(float2*)&dst[(size_t)m * Dd + n] = make_float2(v0, v1);
                } else {
                    const int h = n >> 6, dh = n & 63;
                    const int b = m >> 11, t = m & (Tt - 1);
                    *(float2*)&dst[((size_t)(b * Hh + h) * Tt + t) * DHd + dh] =
                        make_float2(v0, v1);
                }
            }
        }
    }
}

// ---------------------------------------------------------------------------
// Pass 1: per-chunk local stats  KtV[d][e] = sum_i K[i][d]*V[i][e], ksum[d]
// ---------------------------------------------------------------------------
__global__ __launch_bounds__(256, 4)
void chunk_stats_kernel()
{
    __shared__ float sK[CHK * DHd];
    __shared__ float sV[CHK * DHd];
    const int g = blockIdx.x, c = blockIdx.y;
    const int tid = threadIdx.x;
    const float* Kg = g_k + ((size_t)g * Tt + c * CHK) * DHd;
    const float* Vg = g_v + ((size_t)g * Tt + c * CHK) * DHd;

    for (int i = tid; i < CHK * DHd / 4; i += 256) {
        ((float4*)sK)[i] = ((const float4*)Kg)[i];
        ((float4*)sV)[i] = ((const float4*)Vg)[i];
    }
    __syncthreads();

    const int tx = tid & 15, ty = tid >> 4;
    const int d0 = ty * 4, e0 = tx * 4;
    float acc[4][4];
    #pragma unroll
    for (int u = 0; u < 4; u++)
        #pragma unroll
        for (int v = 0; v < 4; v++) acc[u][v] = 0.f;

    for (int i = 0; i < CHK; i++) {
        float4 a = *(const float4*)&sK[i * DHd + d0];
        float4 b = *(const float4*)&sV[i * DHd + e0];
        float ar[4] = {a.x, a.y, a.z, a.w};
        float br[4] = {b.x, b.y, b.z, b.w};
        #pragma unroll
        for (int u = 0; u < 4; u++)
            #pragma unroll
            for (int v = 0; v < 4; v++)
                acc[u][v] = fmaf(ar[u], br[v], acc[u][v]);
    }

    float* outp = g_state + ((size_t)g * NCk + c) * DHd * DHd;
    #pragma unroll
    for (int u = 0; u < 4; u++)
        *(float4*)&outp[(d0 + u) * DHd + e0] =
            make_float4(acc[u][0], acc[u][1], acc[u][2], acc[u][3]);

    if (tid < DHd) {
        float s = 0.f;
        for (int i = 0; i < CHK; i++) s += sK[i * DHd + tid];
        g_zsum[((size_t)g * NCk + c) * DHd + tid] = s;
    }
}

// ---------------------------------------------------------------------------
// Pass 2: exclusive prefix over chunks (batched loads -> register scan)
// ---------------------------------------------------------------------------
__global__ void scan_state_kernel()
{
    const int g = blockIdx.x;
    const int j = blockIdx.y * 256 + threadIdx.x;   // < 4096
    float* base = g_state + (size_t)g * NCk * DHd * DHd + j;
    float r[NCk];
    #pragma unroll
    for (int c = 0; c < NCk; c++) r[c] = base[(size_t)c * DHd * DHd];
    float run = 0.f;
    #pragma unroll
    for (int c = 0; c < NCk; c++) {
        base[(size_t)c * DHd * DHd] = run;
        run += r[c];
    }
}

__global__ void scan_z_kernel()
{
    const int g = blockIdx.x;
    const int j = threadIdx.x;  // < 64
    float* base = g_zsum + (size_t)g * NCk * DHd + j;
    float r[NCk];
    #pragma unroll
    for (int c = 0; c < NCk; c++) r[c] = base[c * DHd];
    float run = 0.f;
    #pragma unroll
    for (int c = 0; c < NCk; c++) {
        base[c * DHd] = run;
        run += r[c];
    }
}

// ---------------------------------------------------------------------------
// Pass 3: per-chunk output.  out = (maskedA@V + Q@S) / max(denom, eps)
// Writes bf16 hi/lo split directly (feeds final GEMM).
// ---------------------------------------------------------------------------
__global__ __launch_bounds__(256)
void attn_out_kernel()
{
    extern __shared__ float sm[];
    float* sQ   = sm;            // 4096 (pitch 64)
    float* sKV  = sQ + 4096;     // 4160 (K pitch 65, then V pitch 64)
    float* sS   = sKV + 4160;    // 4096 (pitch 64)
    float* sA   = sS + 4096;     // 4096 (pitch 64)
    float* zrun = sA + 4096;     // 64
    float* sden = zrun + 64;     // 64

    const int g = blockIdx.x, c = blockIdx.y;
    const int tid = threadIdx.x;
    const float* Qg = g_q + ((size_t)g * Tt + c * CHK) * DHd;
    const float* Kg = g_k + ((size_t)g * Tt + c * CHK) * DHd;
    const float* Vg = g_v + ((size_t)g * Tt + c * CHK) * DHd;
    const float* Sg = g_state + ((size_t)g * NCk + c) * DHd * DHd;

    for (int i = tid; i < 1024; i += 256) {
        ((float4*)sQ)[i] = ((const float4*)Qg)[i];
        ((float4*)sS)[i] = ((const float4*)Sg)[i];
        float4 kv = ((const float4*)Kg)[i];
        int j = i * 4;
        int r = j >> 6, col = j & 63;
        float* p = sKV + r * 65 + col;
        p[0] = kv.x; p[1] = kv.y; p[2] = kv.z; p[3] = kv.w;
    }
    if (tid < DHd) zrun[tid] = g_zsum[((size_t)g * NCk + c) * DHd + tid];
    __syncthreads();

    const int tx = tid & 15, ty = tid >> 4;
    const int i0 = ty * 4, j0 = tx * 4;

    // A = (Q K^T) masked causal (inclusive)
    {
        float acc[4][4];
        #pragma unroll
        for (int u = 0; u < 4; u++)
            #pragma unroll
            for (int v = 0; v < 4; v++) acc[u][v] = 0.f;
        for (int d = 0; d < DHd; d++) {
            float a[4], b[4];
            #pragma unroll
            for (int u = 0; u < 4; u++) a[u] = sQ[(i0 + u) * 64 + d];
            #pragma unroll
            for (int v = 0; v < 4; v++) b[v] = sKV[(j0 + v) * 65 + d];
            #pragma unroll
            for (int u = 0; u < 4; u++)
                #pragma unroll
                for (int v = 0; v < 4; v++)
                    acc[u][v] = fmaf(a[u], b[v], acc[u][v]);
        }
        #pragma unroll
        for (int u = 0; u < 4; u++)
            #pragma unroll
            for (int v = 0; v < 4; v++)
                sA[(i0 + u) * 64 + j0 + v] = (j0 + v <= i0 + u) ? acc[u][v] : 0.f;
    }
    __syncthreads();

    for (int i = tid; i < 1024; i += 256)
        ((float4*)sKV)[i] = ((const float4*)Vg)[i];
    if (tid < CHK) {
        float s = 0.f;
        for (int j = 0; j < CHK; j++) s += sA[tid * 64 + j];
        for (int d = 0; d < DHd; d++) s = fmaf(sQ[tid * 64 + d], zrun[d], s);
        sden[tid] = fmaxf(s, EPSv);
    }
    __syncthreads();

    {
        const int e0 = j0;
        float acc[4][4];
        #pragma unroll
        for (int u = 0; u < 4; u++)
            #pragma unroll
            for (int v = 0; v < 4; v++) acc[u][v] = 0.f;

        for (int j = 0; j < CHK; j++) {
            float4 b4 = *(const float4*)&sKV[j * 64 + e0];
            float b[4] = {b4.x, b4.y, b4.z, b4.w};
            float a[4];
            #pragma unroll
            for (int u = 0; u < 4; u++) a[u] = sA[(i0 + u) * 64 + j];
            #pragma unroll
            for (int u = 0; u < 4; u++)
                #pragma unroll
                for (int v = 0; v < 4; v++)
                    acc[u][v] = fmaf(a[u], b[v], acc[u][v]);
        }
        for (int d = 0; d < DHd; d++) {
            float4 b4 = *(const float4*)&sS[d * 64 + e0];
            float b[4] = {b4.x, b4.y, b4.z, b4.w};
            float a[4];
            #pragma unroll
            for (int u = 0; u < 4; u++) a[u] = sQ[(i0 + u) * 64 + d];
            #pragma unroll
            for (int u = 0; u < 4; u++)
                #pragma unroll
                for (int v = 0; v < 4; v++)
                    acc[u][v] = fmaf(a[u], b[v], acc[u][v]);
        }

        const int b = g / Hh, h = g % Hh;
        #pragma unroll
        for (int u = 0; u < 4; u++) {
            int t = c * CHK + i0 + u;
            float inv = 1.f / sden[i0 + u];
            float4 o = make_float4(acc[u][0] * inv, acc[u][1] * inv,
                                   acc[u][2] * inv, acc[u][3] * inv);
            size_t idx = ((size_t)(b * Tt + t) * Hh + h) * DHd + e0;
            uint2 hi, lo;
            split_bf16x4(o, hi, lo);
            *(uint2*)&g_ahi[idx] = hi;
            *(uint2*)&g_alo[idx] = lo;
        }
    }
}

// ---------------------------------------------------------------------------
extern "C" void kernel_launch(void* const* d_in, const int* in_sizes, int n_in,
                              void* d_out, int out_size)
{
    const float* x  = (const float*)d_in[0];
    const float* Wq = (const float*)d_in[1];
    const float* bq = (const float*)d_in[2];
    const float* Wk = (const float*)d_in[3];
    const float* bk = (const float*)d_in[4];
    const float* Wv = (const float*)d_in[5];
    const float* bv = (const float*)d_in[6];
    const float* Wo = (const float*)d_in[7];
    const float* bo = (const float*)d_in[8];
    float* out = (float*)d_out;

    float *pq, *pk, *pv;
    __nv_bfloat16 *pxhi, *pxlo, *pwhi, *pwlo, *pahi, *palo;
    cudaGetSymbolAddress((void**)&pq,   g_q);
    cudaGetSymbolAddress((void**)&pk,   g_k);
    cudaGetSymbolAddress((void**)&pv,   g_v);
    cudaGetSymbolAddress((void**)&pxhi, g_xhi);
    cudaGetSymbolAddress((void**)&pxlo, g_xlo);
    cudaGetSymbolAddress((void**)&pwhi, g_whi);
    cudaGetSymbolAddress((void**)&pwlo, g_wlo);
    cudaGetSymbolAddress((void**)&pahi, g_ahi);
    cudaGetSymbolAddress((void**)&palo, g_alo);

    static int attr_done = 0;
    if (!attr_done) {
        cudaFuncSetAttribute(mma_gemm_kernel,
                             cudaFuncAttributeMaxDynamicSharedMemorySize, SMEM_GEMM);
        cudaFuncSetAttribute(attn_out_kernel,
                             cudaFuncAttributeMaxDynamicSharedMemorySize,
                             (4096 + 4160 + 4096 + 4096 + 64 + 64) * (int)sizeof(float));
        attr_done = 1;
    }
    const int smem3 = (4096 + 4160 + 4096 + 4096 + 64 + 64) * sizeof(float);

    // --- split fp32 -> bf16 hi/lo ---
    const int xN4 = Mrows * Dd / 4;       // 1M
    const int wN4 = Dd * Dd / 4;          // 256K per matrix
    split_x_kernel<<<(xN4 + 255) / 256, 256>>>((const float4*)x,
        (uint2*)pxhi, (uint2*)pxlo, xN4);
    split_w_kernel<<<(4 * wN4) / 256, 256>>>(
        (const float4*)Wq, (const float4*)Wk, (const float4*)Wv, (const float4*)Wo,
        (uint2*)pwhi, (uint2*)pwlo);

    // --- Q/K/V projections in one batched launch (tensor cores) ---
    dim3 gQKV(Mrows / 128, Dd / 128, 3);   // (32, 8, 3)
    mma_gemm_kernel<<<gQKV, 256, SMEM_GEMM>>>(pxhi, pxlo, pwhi, pwlo,
        bq, bk, bv, pq, pk, pv, 0);

    // --- linear attention ---
    chunk_stats_kernel<<<dim3(Gheads, NCk), 256>>>();
    scan_state_kernel<<<dim3(Gheads, DHd * DHd / 256), 256>>>();
    scan_z_kernel<<<Gheads, DHd>>>();
    attn_out_kernel<<<dim3(Gheads, NCk), 256, smem3>>>();

    // --- output projection ---
    dim3 gOut(Mrows / 128, Dd / 128, 1);
    mma_gemm_kernel<<<gOut, 256, SMEM_GEMM>>>(pahi, palo,
        pwhi + 3 * (size_t)Dd * Dd, pwlo + 3 * (size_t)Dd * Dd,
        bo, bo, bo, out, out, out, 2);
}

// round 6
// speedup vs baseline: 2.2522x; 1.0205x over previous
#include <cuda_runtime.h>
#include <cuda_bf16.h>
#include <cstdint>
#include <math.h>

// Problem constants
#define Bb   2
#define Tt   2048
#define Dd   1024
#define Hh   16
#define DHd  64
#define Mrows (Bb*Tt)      // 4096
#define Gheads (Bb*Hh)     // 32
#define CHK  64
#define NCk  (Tt/CHK)      // 32
#define EPSv 1e-6f

// Scratch (device globals: allocation-free per harness rules)
__device__ float g_q[Gheads*Tt*DHd];
__device__ float g_k[Gheads*Tt*DHd];
__device__ float g_v[Gheads*Tt*DHd];
__device__ float g_state[Gheads*NCk*DHd*DHd];
__device__ float g_zsum[Gheads*NCk*DHd];

// bf16 hi/lo split buffers
__device__ __align__(16) __nv_bfloat16 g_xhi[Mrows*Dd];
__device__ __align__(16) __nv_bfloat16 g_xlo[Mrows*Dd];
__device__ __align__(16) __nv_bfloat16 g_whi[4*Dd*Dd];
__device__ __align__(16) __nv_bfloat16 g_wlo[4*Dd*Dd];
__device__ __align__(16) __nv_bfloat16 g_ahi[Mrows*Dd];
__device__ __align__(16) __nv_bfloat16 g_alo[Mrows*Dd];

// ===========================================================================
// helpers
// ===========================================================================
__device__ __forceinline__ uint32_t smem_to_u32(const void* p) {
    uint32_t a;
    asm("{ .reg .u64 t; cvta.to.shared.u64 t, %1; cvt.u32.u64 %0, t; }"
        : "=r"(a) : "l"(p));
    return a;
}

__device__ __forceinline__ void cp16(uint32_t saddr, const void* g) {
    asm volatile("cp.async.cg.shared.global [%0], [%1], 16;"
                 :: "r"(saddr), "l"(g));
}
#define CP_COMMIT() asm volatile("cp.async.commit_group;" ::: "memory")
#define CP_WAIT1()  asm volatile("cp.async.wait_group 1;" ::: "memory")

#define LDSM4(r, addr) \
    asm volatile("ldmatrix.sync.aligned.m8n8.x4.shared.b16 {%0,%1,%2,%3}, [%4];" \
                 : "=r"((r)[0]), "=r"((r)[1]), "=r"((r)[2]), "=r"((r)[3]) \
                 : "r"(addr))

__device__ __forceinline__ void mma16816(float* c, const uint32_t* a, const uint32_t* b) {
    asm volatile(
        "mma.sync.aligned.m16n8k16.row.col.f32.bf16.bf16.f32 "
        "{%0,%1,%2,%3}, {%4,%5,%6,%7}, {%8,%9}, {%0,%1,%2,%3};"
        : "+f"(c[0]), "+f"(c[1]), "+f"(c[2]), "+f"(c[3])
        : "r"(a[0]), "r"(a[1]), "r"(a[2]), "r"(a[3]), "r"(b[0]), "r"(b[1]));
}

// fp32 float4 -> packed hi/lo bf16 (4 each, as uint2)
__device__ __forceinline__ void split_bf16x4(float4 a, uint2& hi, uint2& lo)
{
    __nv_bfloat16 h0 = __float2bfloat16(a.x);
    __nv_bfloat16 h1 = __float2bfloat16(a.y);
    __nv_bfloat16 h2 = __float2bfloat16(a.z);
    __nv_bfloat16 h3 = __float2bfloat16(a.w);
    __nv_bfloat16 l0 = __float2bfloat16(a.x - __bfloat162float(h0));
    __nv_bfloat16 l1 = __float2bfloat16(a.y - __bfloat162float(h1));
    __nv_bfloat16 l2 = __float2bfloat16(a.z - __bfloat162float(h2));
    __nv_bfloat16 l3 = __float2bfloat16(a.w - __bfloat162float(h3));
    hi.x = (uint32_t)__bfloat16_as_ushort(h0) | ((uint32_t)__bfloat16_as_ushort(h1) << 16);
    hi.y = (uint32_t)__bfloat16_as_ushort(h2) | ((uint32_t)__bfloat16_as_ushort(h3) << 16);
    lo.x = (uint32_t)__bfloat16_as_ushort(l0) | ((uint32_t)__bfloat16_as_ushort(l1) << 16);
    lo.y = (uint32_t)__bfloat16_as_ushort(l2) | ((uint32_t)__bfloat16_as_ushort(l3) << 16);
}

// ===========================================================================
// split kernels: fp32 -> bf16 hi/lo
// ===========================================================================
__global__ void split_x_kernel(const float4* __restrict__ src,
                               uint2* __restrict__ hi, uint2* __restrict__ lo, int n4)
{
    int i = blockIdx.x * blockDim.x + threadIdx.x;
    if (i >= n4) return;
    float4 v = __ldg(&src[i]);
    uint2 h, l;
    split_bf16x4(v, h, l);
    hi[i] = h;
    lo[i] = l;
}

// all 4 weight matrices in one launch; quarter = i >> 18 (Dd*Dd/4 = 2^18)
__global__ void split_w_kernel(const float4* __restrict__ w0,
                               const float4* __restrict__ w1,
                               const float4* __restrict__ w2,
                               const float4* __restrict__ w3,
                               uint2* __restrict__ hi, uint2* __restrict__ lo)
{
    int i = blockIdx.x * blockDim.x + threadIdx.x;
    const int quarter = i >> 18;
    const int r = i & ((1 << 18) - 1);
    const float4* src = (quarter == 0) ? w0 : (quarter == 1) ? w1
                       : (quarter == 2) ? w2 : w3;
    float4 v = __ldg(&src[r]);
    uint2 h, l;
    split_bf16x4(v, h, l);
    hi[i] = h;
    lo[i] = l;
}

// ===========================================================================
// Tensor-core GEMM via mma.sync (bf16x3 split):
// C[M=4096,N=1024] = A[M,K=1024] @ W[N,K]^T + bias
// CTA tile 128x256, warp tile 64x64, BK=32, 3-stage cp.async.
// Batched over blockIdx.z. mode 0 (qkv): z=0,1 ELU+1; z=2 plain, [g][t][dh]
// mode 2: plain row-major [M][N]
// ===========================================================================
#define BKc   32                 // bf16 K per chunk
#define NCH   (Dd/BKc)           // 32
#define SSTR  40                 // smem row stride (bf16): 32 data + 8 pad
#define A_SMB (128*SSTR*2)       // 10240 B
#define W_SMB (256*SSTR*2)       // 20480 B
#define STAGE_SMB (2*A_SMB + 2*W_SMB)  // 61440 B
#define NSTAGE 3
#define SMEM_GEMM (NSTAGE*STAGE_SMB)   // 184320 B

__global__ __launch_bounds__(256, 1)
void mma_gemm_kernel(const __nv_bfloat16* __restrict__ Ahi,
                     const __nv_bfloat16* __restrict__ Alo,
                     const __nv_bfloat16* __restrict__ WhiB,
                     const __nv_bfloat16* __restrict__ WloB,
                     const float* __restrict__ b0,
                     const float* __restrict__ b1,
                     const float* __restrict__ b2,
                     float* __restrict__ d0,
                     float* __restrict__ d1,
                     float* __restrict__ d2,
                     int mode)
{
    extern __shared__ char smem[];
    const uint32_t sb = smem_to_u32(smem);
    const int tid  = threadIdx.x;
    const int lane = tid & 31, wid = tid >> 5;
    const int m0 = blockIdx.x * 128, n0 = blockIdx.y * 256;
    const int z  = blockIdx.z;

    const __nv_bfloat16* Whi = WhiB + (size_t)z * Dd * Dd;
    const __nv_bfloat16* Wlo = WloB + (size_t)z * Dd * Dd;
    const float* bias = (z == 0) ? b0 : (z == 1) ? b1 : b2;
    float* dst        = (z == 0) ? d0 : (z == 1) ? d1 : d2;
    const bool do_elu = (mode == 0) && (z < 2);

    // ---- loader mapping: 4 groups x 64 threads ----
    // grp0: Ahi (512 16B-chunks), grp1: Alo, grp2: Whi (1024), grp3: Wlo
    const int grp = tid >> 6;
    const int lt  = tid & 63;
    const __nv_bfloat16* gtile;
    uint32_t toff;
    if      (grp == 0) { gtile = Ahi + (size_t)m0 * Dd; toff = 0; }
    else if (grp == 1) { gtile = Alo + (size_t)m0 * Dd; toff = A_SMB; }
    else if (grp == 2) { gtile = Whi + (size_t)n0 * Dd; toff = 2*A_SMB; }
    else               { gtile = Wlo + (size_t)n0 * Dd; toff = 2*A_SMB + W_SMB; }
    const bool isW = (grp >= 2);

    float acc[4][8][4];
    #pragma unroll
    for (int a = 0; a < 4; a++)
        #pragma unroll
        for (int b = 0; b < 8; b++)
            #pragma unroll
            for (int c = 0; c < 4; c++) acc[a][b][c] = 0.f;

    // issue loads of chunk kc into stage kc%NSTAGE
    auto issue = [&](int kc) {
        const uint32_t stb = sb + (kc % NSTAGE) * STAGE_SMB + toff;
        const __nv_bfloat16* g = gtile + kc * BKc;
        #pragma unroll
        for (int j = 0; j < 16; j++) {
            if (j < 8 || isW) {
                int chunk = lt + j * 64;       // A: 0..511, W: 0..1023
                int row = chunk >> 2;
                int c8  = (chunk & 3) * 8;
                cp16(stb + (uint32_t)(row * SSTR + c8) * 2,
                     g + (size_t)row * Dd + c8);
            }
        }
    };

    issue(0); CP_COMMIT();
    issue(1); CP_COMMIT();

    // warp layout: 2 (M) x 4 (N); warp tile 64x64
    const int wm = (wid & 1) * 64;
    const int wn = (wid >> 1) * 64;
    const int arow = (lane & 7) + ((lane >> 3) & 1) * 8;
    const int acol = ((lane >> 4) & 1) * 8;
    const int brow = (lane & 7) + ((lane >> 4) & 1) * 8;
    const int bcol = ((lane >> 3) & 1) * 8;

    for (int kc = 0; kc < NCH; kc++) {
        CP_WAIT1();
        __syncthreads();
        if (kc + 2 < NCH) { issue(kc + 2); CP_COMMIT(); }

        const uint32_t stb = sb + (kc % NSTAGE) * STAGE_SMB;
        const uint32_t aH = stb;
        const uint32_t aL = stb + A_SMB;
        const uint32_t wH = stb + 2 * A_SMB;
        const uint32_t wL = stb + 2 * A_SMB + W_SMB;

        #pragma unroll
        for (int ks = 0; ks < 2; ks++) {
            uint32_t ah[4][4], al[4][4];
            #pragma unroll
            for (int mi = 0; mi < 4; mi++) {
                uint32_t off = (uint32_t)((wm + mi * 16 + arow) * SSTR + ks * 16 + acol) * 2;
                LDSM4(ah[mi], aH + off);
                LDSM4(al[mi], aL + off);
            }
            #pragma unroll
            for (int nj = 0; nj < 4; nj++) {
                uint32_t bh[4], bl[4];
                uint32_t off = (uint32_t)((wn + nj * 16 + brow) * SSTR + ks * 16 + bcol) * 2;
                LDSM4(bh, wH + off);
                LDSM4(bl, wL + off);
                #pragma unroll
                for (int mi = 0; mi < 4; mi++)
                    #pragma unroll
                    for (int hf = 0; hf < 2; hf++) {
                        const int ni = nj * 2 + hf;
                        mma16816(acc[mi][ni], ah[mi], &bh[hf * 2]);
                        mma16816(acc[mi][ni], ah[mi], &bl[hf * 2]);
                        mma16816(acc[mi][ni], al[mi], &bh[hf * 2]);
                    }
            }
        }
    }

    // ---- epilogue ----
    const int gid = lane >> 2, qid = lane & 3;
    float bv[16];
    #pragma unroll
    for (int ni = 0; ni < 8; ni++) {
        int n = n0 + wn + ni * 8 + qid * 2;
        bv[2 * ni]     = __ldg(&bias[n]);
        bv[2 * ni + 1] = __ldg(&bias[n + 1]);
    }

    #pragma unroll
    for (int mi = 0; mi < 4; mi++) {
        #pragma unroll
        for (int rr = 0; rr < 2; rr++) {
            const int m = m0 + wm + mi * 16 + gid + rr * 8;
            #pragma unroll
            for (int ni = 0; ni < 8; ni++) {
                const int n = n0 + wn + ni * 8 + qid * 2;
                float v0 = acc[mi][ni][rr * 2 + 0] + bv[2 * ni];
                float v1 = acc[mi][ni][rr * 2 + 1] + bv[2 * ni + 1];
                if (do_elu) {
                    v0 = (v0 > 0.f) ? (v0 + 1.f) : expf(v0);
                    v1 = (v1 > 0.f) ? (v1 + 1.f) : expf(v1);
                }
                if (mode == 2) {
                    *(float2*)&dst[(size_t)m * Dd + n] = make_float2(v0, v1);
                } else {
                    const int h = n >> 6, dh = n & 63;
                    const int b = m >> 11, t = m & (Tt - 1);
                    *(float2*)&dst[((size_t)(b * Hh + h) * Tt + t) * DHd + dh] =
                        make_float2(v0, v1);
                }
            }
        }
    }
}

// ---------------------------------------------------------------------------
// Pass 1: per-chunk local stats  KtV[d][e] = sum_i K[i][d]*V[i][e], ksum[d]
// 64 threads, 8x8 register tile per thread (FMA/byte = 1.0)
// ---------------------------------------------------------------------------
__global__ __launch_bounds__(64)
void chunk_stats_kernel()
{
    __shared__ float sK[CHK * DHd];
    __shared__ float sV[CHK * DHd];
    const int g = blockIdx.x, c = blockIdx.y;
    const int tid = threadIdx.x;
    const float* Kg = g_k + ((size_t)g * Tt + c * CHK) * DHd;
    const float* Vg = g_v + ((size_t)g * Tt + c * CHK) * DHd;

    for (int i = tid; i < CHK * DHd / 4; i += 64) {
        ((float4*)sK)[i] = ((const float4*)Kg)[i];
        ((float4*)sV)[i] = ((const float4*)Vg)[i];
    }
    __syncthreads();

    const int tx = tid & 7, ty = tid >> 3;
    const int d0 = ty * 8, e0 = tx * 8;
    float acc[8][8];
    #pragma unroll
    for (int u = 0; u < 8; u++)
        #pragma unroll
        for (int v = 0; v < 8; v++) acc[u][v] = 0.f;

    for (int i = 0; i < CHK; i++) {
        float a[8], b[8];
        *(float4*)(a)     = *(const float4*)&sK[i * DHd + d0];
        *(float4*)(a + 4) = *(const float4*)&sK[i * DHd + d0 + 4];
        *(float4*)(b)     = *(const float4*)&sV[i * DHd + e0];
        *(float4*)(b + 4) = *(const float4*)&sV[i * DHd + e0 + 4];
        #pragma unroll
        for (int u = 0; u < 8; u++)
            #pragma unroll
            for (int v = 0; v < 8; v++)
                acc[u][v] = fmaf(a[u], b[v], acc[u][v]);
    }

    float* outp = g_state + ((size_t)g * NCk + c) * DHd * DHd;
    #pragma unroll
    for (int u = 0; u < 8; u++) {
        *(float4*)&outp[(d0 + u) * DHd + e0] =
            make_float4(acc[u][0], acc[u][1], acc[u][2], acc[u][3]);
        *(float4*)&outp[(d0 + u) * DHd + e0 + 4] =
            make_float4(acc[u][4], acc[u][5], acc[u][6], acc[u][7]);
    }

    {
        float s = 0.f;
        for (int i = 0; i < CHK; i++) s += sK[i * DHd + tid];
        g_zsum[((size_t)g * NCk + c) * DHd + tid] = s;
    }
}

// ---------------------------------------------------------------------------
// Pass 2: exclusive prefix over chunks (batched loads -> register scan)
// ---------------------------------------------------------------------------
__global__ void scan_state_kernel()
{
    const int g = blockIdx.x;
    const int j = blockIdx.y * 256 + threadIdx.x;   // < 4096
    float* base = g_state + (size_t)g * NCk * DHd * DHd + j;
    float r[NCk];
    #pragma unroll
    for (int c = 0; c < NCk; c++) r[c] = base[(size_t)c * DHd * DHd];
    float run = 0.f;
    #pragma unroll
    for (int c = 0; c < NCk; c++) {
        base[(size_t)c * DHd * DHd] = run;
        run += r[c];
    }
}

__global__ void scan_z_kernel()
{
    const int g = blockIdx.x;
    const int j = threadIdx.x;  // < 64
    float* base = g_zsum + (size_t)g * NCk * DHd + j;
    float r[NCk];
    #pragma unroll
    for (int c = 0; c < NCk; c++) r[c] = base[c * DHd];
    float run = 0.f;
    #pragma unroll
    for (int c = 0; c < NCk; c++) {
        base[c * DHd] = run;
        run += r[c];
    }
}

// ---------------------------------------------------------------------------
// Pass 3: per-chunk output.  out = (maskedA@V + Q@S) / max(denom, eps)
// Writes bf16 hi/lo split directly (feeds final GEMM).
// ---------------------------------------------------------------------------
__global__ __launch_bounds__(256)
void attn_out_kernel()
{
    extern __shared__ float sm[];
    float* sQ   = sm;            // 4096 (pitch 64)
    float* sKV  = sQ + 4096;     // 4160 (K pitch 65, then V pitch 64)
    float* sS   = sKV + 4160;    // 4096 (pitch 64)
    float* sA   = sS + 4096;     // 4096 (pitch 64)
    float* zrun = sA + 4096;     // 64
    float* sden = zrun + 64;     // 64

    const int g = blockIdx.x, c = blockIdx.y;
    const int tid = threadIdx.x;
    const float* Qg = g_q + ((size_t)g * Tt + c * CHK) * DHd;
    const float* Kg = g_k + ((size_t)g * Tt + c * CHK) * DHd;
    const float* Vg = g_v + ((size_t)g * Tt + c * CHK) * DHd;
    const float* Sg = g_state + ((size_t)g * NCk + c) * DHd * DHd;

    for (int i = tid; i < 1024; i += 256) {
        ((float4*)sQ)[i] = ((const float4*)Qg)[i];
        ((float4*)sS)[i] = ((const float4*)Sg)[i];
        float4 kv = ((const float4*)Kg)[i];
        int j = i * 4;
        int r = j >> 6, col = j & 63;
        float* p = sKV + r * 65 + col;
        p[0] = kv.x; p[1] = kv.y; p[2] = kv.z; p[3] = kv.w;
    }
    if (tid < DHd) zrun[tid] = g_zsum[((size_t)g * NCk + c) * DHd + tid];
    __syncthreads();

    const int tx = tid & 15, ty = tid >> 4;
    const int i0 = ty * 4, j0 = tx * 4;

    // A = (Q K^T) masked causal (inclusive)
    {
        float acc[4][4];
        #pragma unroll
        for (int u = 0; u < 4; u++)
            #pragma unroll
            for (int v = 0; v < 4; v++) acc[u][v] = 0.f;
        for (int d = 0; d < DHd; d++) {
            float a[4], b[4];
            #pragma unroll
            for (int u = 0; u < 4; u++) a[u] = sQ[(i0 + u) * 64 + d];
            #pragma unroll
            for (int v = 0; v < 4; v++) b[v] = sKV[(j0 + v) * 65 + d];
            #pragma unroll
            for (int u = 0; u < 4; u++)
                #pragma unroll
                for (int v = 0; v < 4; v++)
                    acc[u][v] = fmaf(a[u], b[v], acc[u][v]);
        }
        #pragma unroll
        for (int u = 0; u < 4; u++)
            #pragma unroll
            for (int v = 0; v < 4; v++)
                sA[(i0 + u) * 64 + j0 + v] = (j0 + v <= i0 + u) ? acc[u][v] : 0.f;
    }
    __syncthreads();

    for (int i = tid; i < 1024; i += 256)
        ((float4*)sKV)[i] = ((const float4*)Vg)[i];
    if (tid < CHK) {
        float s = 0.f;
        for (int j = 0; j < CHK; j++) s += sA[tid * 64 + j];
        for (int d = 0; d < DHd; d++) s = fmaf(sQ[tid * 64 + d], zrun[d], s);
        sden[tid] = fmaxf(s, EPSv);
    }
    __syncthreads();

    {
        const int e0 = j0;
        float acc[4][4];
        #pragma unroll
        for (int u = 0; u < 4; u++)
            #pragma unroll
            for (int v = 0; v < 4; v++) acc[u][v] = 0.f;

        for (int j = 0; j < CHK; j++) {
            float4 b4 = *(const float4*)&sKV[j * 64 + e0];
            float b[4] = {b4.x, b4.y, b4.z, b4.w};
            float a[4];
            #pragma unroll
            for (int u = 0; u < 4; u++) a[u] = sA[(i0 + u) * 64 + j];
            #pragma unroll
            for (int u = 0; u < 4; u++)
                #pragma unroll
                for (int v = 0; v < 4; v++)
                    acc[u][v] = fmaf(a[u], b[v], acc[u][v]);
        }
        for (int d = 0; d < DHd; d++) {
            float4 b4 = *(const float4*)&sS[d * 64 + e0];
            float b[4] = {b4.x, b4.y, b4.z, b4.w};
            float a[4];
            #pragma unroll
            for (int u = 0; u < 4; u++) a[u] = sQ[(i0 + u) * 64 + d];
            #pragma unroll
            for (int u = 0; u < 4; u++)
                #pragma unroll
                for (int v = 0; v < 4; v++)
                    acc[u][v] = fmaf(a[u], b[v], acc[u][v]);
        }

        const int b = g / Hh, h = g % Hh;
        #pragma unroll
        for (int u = 0; u < 4; u++) {
            int t = c * CHK + i0 + u;
            float inv = 1.f / sden[i0 + u];
            float4 o = make_float4(acc[u][0] * inv, acc[u][1] * inv,
                                   acc[u][2] * inv, acc[u][3] * inv);
            size_t idx = ((size_t)(b * Tt + t) * Hh + h) * DHd + e0;
            uint2 hi, lo;
            split_bf16x4(o, hi, lo);
            *(uint2*)&g_ahi[idx] = hi;
            *(uint2*)&g_alo[idx] = lo;
        }
    }
}

// ---------------------------------------------------------------------------
extern "C" void kernel_launch(void* const* d_in, const int* in_sizes, int n_in,
                              void* d_out, int out_size)
{
    const float* x  = (const float*)d_in[0];
    const float* Wq = (const float*)d_in[1];
    const float* bq = (const float*)d_in[2];
    const float* Wk = (const float*)d_in[3];
    const float* bk = (const float*)d_in[4];
    const float* Wv = (const float*)d_in[5];
    const float* bv = (const float*)d_in[6];
    const float* Wo = (const float*)d_in[7];
    const float* bo = (const float*)d_in[8];
    float* out = (float*)d_out;

    float *pq, *pk, *pv;
    __nv_bfloat16 *pxhi, *pxlo, *pwhi, *pwlo, *pahi, *palo;
    cudaGetSymbolAddress((void**)&pq,   g_q);
    cudaGetSymbolAddress((void**)&pk,   g_k);
    cudaGetSymbolAddress((void**)&pv,   g_v);
    cudaGetSymbolAddress((void**)&pxhi, g_xhi);
    cudaGetSymbolAddress((void**)&pxlo, g_xlo);
    cudaGetSymbolAddress((void**)&pwhi, g_whi);
    cudaGetSymbolAddress((void**)&pwlo, g_wlo);
    cudaGetSymbolAddress((void**)&pahi, g_ahi);
    cudaGetSymbolAddress((void**)&palo, g_alo);

    static int attr_done = 0;
    if (!attr_done) {
        cudaFuncSetAttribute(mma_gemm_kernel,
                             cudaFuncAttributeMaxDynamicSharedMemorySize, SMEM_GEMM);
        cudaFuncSetAttribute(attn_out_kernel,
                             cudaFuncAttributeMaxDynamicSharedMemorySize,
                             (4096 + 4160 + 4096 + 4096 + 64 + 64) * (int)sizeof(float));
        attr_done = 1;
    }
    const int smem3 = (4096 + 4160 + 4096 + 4096 + 64 + 64) * sizeof(float);

    // --- split fp32 -> bf16 hi/lo ---
    const int xN4 = Mrows * Dd / 4;       // 1M
    const int wN4 = Dd * Dd / 4;          // 256K per matrix
    split_x_kernel<<<(xN4 + 255) / 256, 256>>>((const float4*)x,
        (uint2*)pxhi, (uint2*)pxlo, xN4);
    split_w_kernel<<<(4 * wN4) / 256, 256>>>(
        (const float4*)Wq, (const float4*)Wk, (const float4*)Wv, (const float4*)Wo,
        (uint2*)pwhi, (uint2*)pwlo);

    // --- Q/K/V projections in one batched launch (tensor cores) ---
    dim3 gQKV(Mrows / 128, Dd / 256, 3);   // (32, 4, 3)
    mma_gemm_kernel<<<gQKV, 256, SMEM_GEMM>>>(pxhi, pxlo, pwhi, pwlo,
        bq, bk, bv, pq, pk, pv, 0);

    // --- linear attention ---
    chunk_stats_kernel<<<dim3(Gheads, NCk), 64>>>();
    scan_state_kernel<<<dim3(Gheads, DHd * DHd / 256), 256>>>();
    scan_z_kernel<<<Gheads, DHd>>>();
    attn_out_kernel<<<dim3(Gheads, NCk), 256, smem3>>>();

    // --- output projection ---
    dim3 gOut(Mrows / 128, Dd / 256, 1);
    mma_gemm_kernel<<<gOut, 256, SMEM_GEMM>>>(pahi, palo,
        pwhi + 3 * (size_t)Dd * Dd, pwlo + 3 * (size_t)Dd * Dd,
        bo, bo, bo, out, out, out, 2);
}

// round 7
// speedup vs baseline: 2.2939x; 1.0185x over previous
#include <cuda_runtime.h>
#include <cuda_bf16.h>
#include <cstdint>
#include <math.h>

// Problem constants
#define Bb   2
#define Tt   2048
#define Dd   1024
#define Hh   16
#define DHd  64
#define Mrows (Bb*Tt)      // 4096
#define Gheads (Bb*Hh)     // 32
#define CHK  64
#define NCk  (Tt/CHK)      // 32
#define EPSv 1e-6f

// Scratch (device globals: allocation-free per harness rules)
__device__ float g_q[Gheads*Tt*DHd];
__device__ float g_k[Gheads*Tt*DHd];
__device__ float g_v[Gheads*Tt*DHd];
__device__ float g_state[Gheads*NCk*DHd*DHd];
__device__ float g_zsum[Gheads*NCk*DHd];

// bf16 hi/lo split buffers
__device__ __align__(16) __nv_bfloat16 g_xhi[Mrows*Dd];
__device__ __align__(16) __nv_bfloat16 g_xlo[Mrows*Dd];
__device__ __align__(16) __nv_bfloat16 g_whi[4*Dd*Dd];
__device__ __align__(16) __nv_bfloat16 g_wlo[4*Dd*Dd];
__device__ __align__(16) __nv_bfloat16 g_ahi[Mrows*Dd];
__device__ __align__(16) __nv_bfloat16 g_alo[Mrows*Dd];

// ===========================================================================
// helpers
// ===========================================================================
__device__ __forceinline__ uint32_t smem_to_u32(const void* p) {
    uint32_t a;
    asm("{ .reg .u64 t; cvta.to.shared.u64 t, %1; cvt.u32.u64 %0, t; }"
        : "=r"(a) : "l"(p));
    return a;
}

__device__ __forceinline__ void cp16(uint32_t saddr, const void* g) {
    asm volatile("cp.async.cg.shared.global [%0], [%1], 16;"
                 :: "r"(saddr), "l"(g));
}
#define CP_COMMIT() asm volatile("cp.async.commit_group;" ::: "memory")
#define CP_WAIT1()  asm volatile("cp.async.wait_group 1;" ::: "memory")

#define LDSM4(r, addr) \
    asm volatile("ldmatrix.sync.aligned.m8n8.x4.shared.b16 {%0,%1,%2,%3}, [%4];" \
                 : "=r"((r)[0]), "=r"((r)[1]), "=r"((r)[2]), "=r"((r)[3]) \
                 : "r"(addr))

__device__ __forceinline__ void mma16816(float* c, const uint32_t* a, const uint32_t* b) {
    asm volatile(
        "mma.sync.aligned.m16n8k16.row.col.f32.bf16.bf16.f32 "
        "{%0,%1,%2,%3}, {%4,%5,%6,%7}, {%8,%9}, {%0,%1,%2,%3};"
        : "+f"(c[0]), "+f"(c[1]), "+f"(c[2]), "+f"(c[3])
        : "r"(a[0]), "r"(a[1]), "r"(a[2]), "r"(a[3]), "r"(b[0]), "r"(b[1]));
}

// fp32 float4 -> packed hi/lo bf16 (4 each, as uint2)
__device__ __forceinline__ void split_bf16x4(float4 a, uint2& hi, uint2& lo)
{
    __nv_bfloat16 h0 = __float2bfloat16(a.x);
    __nv_bfloat16 h1 = __float2bfloat16(a.y);
    __nv_bfloat16 h2 = __float2bfloat16(a.z);
    __nv_bfloat16 h3 = __float2bfloat16(a.w);
    __nv_bfloat16 l0 = __float2bfloat16(a.x - __bfloat162float(h0));
    __nv_bfloat16 l1 = __float2bfloat16(a.y - __bfloat162float(h1));
    __nv_bfloat16 l2 = __float2bfloat16(a.z - __bfloat162float(h2));
    __nv_bfloat16 l3 = __float2bfloat16(a.w - __bfloat162float(h3));
    hi.x = (uint32_t)__bfloat16_as_ushort(h0) | ((uint32_t)__bfloat16_as_ushort(h1) << 16);
    hi.y = (uint32_t)__bfloat16_as_ushort(h2) | ((uint32_t)__bfloat16_as_ushort(h3) << 16);
    lo.x = (uint32_t)__bfloat16_as_ushort(l0) | ((uint32_t)__bfloat16_as_ushort(l1) << 16);
    lo.y = (uint32_t)__bfloat16_as_ushort(l2) | ((uint32_t)__bfloat16_as_ushort(l3) << 16);
}

// ===========================================================================
// split kernels: fp32 -> bf16 hi/lo
// ===========================================================================
__global__ void split_x_kernel(const float4* __restrict__ src,
                               uint2* __restrict__ hi, uint2* __restrict__ lo, int n4)
{
    int i = blockIdx.x * blockDim.x + threadIdx.x;
    if (i >= n4) return;
    float4 v = __ldg(&src[i]);
    uint2 h, l;
    split_bf16x4(v, h, l);
    hi[i] = h;
    lo[i] = l;
}

// all 4 weight matrices in one launch; quarter = i >> 18 (Dd*Dd/4 = 2^18)
__global__ void split_w_kernel(const float4* __restrict__ w0,
                               const float4* __restrict__ w1,
                               const float4* __restrict__ w2,
                               const float4* __restrict__ w3,
                               uint2* __restrict__ hi, uint2* __restrict__ lo)
{
    int i = blockIdx.x * blockDim.x + threadIdx.x;
    const int quarter = i >> 18;
    const int r = i & ((1 << 18) - 1);
    const float4* src = (quarter == 0) ? w0 : (quarter == 1) ? w1
                       : (quarter == 2) ? w2 : w3;
    float4 v = __ldg(&src[r]);
    uint2 h, l;
    split_bf16x4(v, h, l);
    hi[i] = h;
    lo[i] = l;
}

// ===========================================================================
// Tensor-core GEMM via mma.sync (bf16x3 split):
// C[M=4096,N=1024] = A[M,K=1024] @ W[N,K]^T + bias
// CTA tile 128x256, warp tile 64x64, BK=32, 3-stage cp.async.
// Inner loop: 3 product passes over 8 distinct accumulators (no RAW chains).
// ===========================================================================
#define BKc   32                 // bf16 K per chunk
#define NCH   (Dd/BKc)           // 32
#define SSTR  40                 // smem row stride (bf16): 32 data + 8 pad
#define A_SMB (128*SSTR*2)       // 10240 B
#define W_SMB (256*SSTR*2)       // 20480 B
#define STAGE_SMB (2*A_SMB + 2*W_SMB)  // 61440 B
#define NSTAGE 3
#define SMEM_GEMM (NSTAGE*STAGE_SMB)   // 184320 B

__global__ __launch_bounds__(256, 1)
void mma_gemm_kernel(const __nv_bfloat16* __restrict__ Ahi,
                     const __nv_bfloat16* __restrict__ Alo,
                     const __nv_bfloat16* __restrict__ WhiB,
                     const __nv_bfloat16* __restrict__ WloB,
                     const float* __restrict__ b0,
                     const float* __restrict__ b1,
                     const float* __restrict__ b2,
                     float* __restrict__ d0,
                     float* __restrict__ d1,
                     float* __restrict__ d2,
                     int mode)
{
    extern __shared__ char smem[];
    const uint32_t sb = smem_to_u32(smem);
    const int tid  = threadIdx.x;
    const int lane = tid & 31, wid = tid >> 5;
    const int m0 = blockIdx.x * 128, n0 = blockIdx.y * 256;
    const int z  = blockIdx.z;

    const __nv_bfloat16* Whi = WhiB + (size_t)z * Dd * Dd;
    const __nv_bfloat16* Wlo = WloB + (size_t)z * Dd * Dd;
    const float* bias = (z == 0) ? b0 : (z == 1) ? b1 : b2;
    float* dst        = (z == 0) ? d0 : (z == 1) ? d1 : d2;
    const bool do_elu = (mode == 0) && (z < 2);

    // ---- loader mapping: 4 groups x 64 threads ----
    const int grp = tid >> 6;
    const int lt  = tid & 63;
    const __nv_bfloat16* gtile;
    uint32_t toff;
    if      (grp == 0) { gtile = Ahi + (size_t)m0 * Dd; toff = 0; }
    else if (grp == 1) { gtile = Alo + (size_t)m0 * Dd; toff = A_SMB; }
    else if (grp == 2) { gtile = Whi + (size_t)n0 * Dd; toff = 2*A_SMB; }
    else               { gtile = Wlo + (size_t)n0 * Dd; toff = 2*A_SMB + W_SMB; }
    const bool isW = (grp >= 2);

    float acc[4][8][4];
    #pragma unroll
    for (int a = 0; a < 4; a++)
        #pragma unroll
        for (int b = 0; b < 8; b++)
            #pragma unroll
            for (int c = 0; c < 4; c++) acc[a][b][c] = 0.f;

    // issue loads of chunk kc into stage kc%NSTAGE
    auto issue = [&](int kc) {
        const uint32_t stb = sb + (kc % NSTAGE) * STAGE_SMB + toff;
        const __nv_bfloat16* g = gtile + kc * BKc;
        #pragma unroll
        for (int j = 0; j < 16; j++) {
            if (j < 8 || isW) {
                int chunk = lt + j * 64;       // A: 0..511, W: 0..1023
                int row = chunk >> 2;
                int c8  = (chunk & 3) * 8;
                cp16(stb + (uint32_t)(row * SSTR + c8) * 2,
                     g + (size_t)row * Dd + c8);
            }
        }
    };

    issue(0); CP_COMMIT();
    issue(1); CP_COMMIT();

    // warp layout: 2 (M) x 4 (N); warp tile 64x64
    const int wm = (wid & 1) * 64;
    const int wn = (wid >> 1) * 64;
    const int arow = (lane & 7) + ((lane >> 3) & 1) * 8;
    const int acol = ((lane >> 4) & 1) * 8;
    const int brow = (lane & 7) + ((lane >> 4) & 1) * 8;
    const int bcol = ((lane >> 3) & 1) * 8;

    for (int kc = 0; kc < NCH; kc++) {
        CP_WAIT1();
        __syncthreads();
        if (kc + 2 < NCH) { issue(kc + 2); CP_COMMIT(); }

        const uint32_t stb = sb + (kc % NSTAGE) * STAGE_SMB;
        const uint32_t aH = stb;
        const uint32_t aL = stb + A_SMB;
        const uint32_t wH = stb + 2 * A_SMB;
        const uint32_t wL = stb + 2 * A_SMB + W_SMB;

        #pragma unroll
        for (int ks = 0; ks < 2; ks++) {
            uint32_t ah[4][4], al[4][4];
            #pragma unroll
            for (int mi = 0; mi < 4; mi++) {
                uint32_t off = (uint32_t)((wm + mi * 16 + arow) * SSTR + ks * 16 + acol) * 2;
                LDSM4(ah[mi], aH + off);
                LDSM4(al[mi], aL + off);
            }
            #pragma unroll
            for (int nj = 0; nj < 4; nj++) {
                uint32_t bh[4], bl[4];
                uint32_t off = (uint32_t)((wn + nj * 16 + brow) * SSTR + ks * 16 + bcol) * 2;
                LDSM4(bh, wH + off);
                LDSM4(bl, wL + off);
                // pass 1: hi*hi over 8 distinct accumulators
                #pragma unroll
                for (int mi = 0; mi < 4; mi++)
                    #pragma unroll
                    for (int hf = 0; hf < 2; hf++)
                        mma16816(acc[mi][nj * 2 + hf], ah[mi], &bh[hf * 2]);
                // pass 2: hi*lo
                #pragma unroll
                for (int mi = 0; mi < 4; mi++)
                    #pragma unroll
                    for (int hf = 0; hf < 2; hf++)
                        mma16816(acc[mi][nj * 2 + hf], ah[mi], &bl[hf * 2]);
                // pass 3: lo*hi
                #pragma unroll
                for (int mi = 0; mi < 4; mi++)
                    #pragma unroll
                    for (int hf = 0; hf < 2; hf++)
                        mma16816(acc[mi][nj * 2 + hf], al[mi], &bh[hf * 2]);
            }
        }
    }

    // ---- epilogue ----
    const int gid = lane >> 2, qid = lane & 3;
    float bv[16];
    #pragma unroll
    for (int ni = 0; ni < 8; ni++) {
        int n = n0 + wn + ni * 8 + qid * 2;
        bv[2 * ni]     = __ldg(&bias[n]);
        bv[2 * ni + 1] = __ldg(&bias[n + 1]);
    }

    #pragma unroll
    for (int mi = 0; mi < 4; mi++) {
        #pragma unroll
        for (int rr = 0; rr < 2; rr++) {
            const int m = m0 + wm + mi * 16 + gid + rr * 8;
            #pragma unroll
            for (int ni = 0; ni < 8; ni++) {
                const int n = n0 + wn + ni * 8 + qid * 2;
                float v0 = acc[mi][ni][rr * 2 + 0] + bv[2 * ni];
                float v1 = acc[mi][ni][rr * 2 + 1] + bv[2 * ni + 1];
                if (do_elu) {
                    v0 = (v0 > 0.f) ? (v0 + 1.f) : expf(v0);
                    v1 = (v1 > 0.f) ? (v1 + 1.f) : expf(v1);
                }
                if (mode == 2) {
                    *(float2*)&dst[(size_t)m * Dd + n] = make_float2(v0, v1);
                } else {
                    const int h = n >> 6, dh = n & 63;
                    const int b = m >> 11, t = m & (Tt - 1);
                    *(float2*)&dst[((size_t)(b * Hh + h) * Tt + t) * DHd + dh] =
                        make_float2(v0, v1);
                }
            }
        }
    }
}

// ---------------------------------------------------------------------------
// Pass 1: per-chunk local stats  KtV[d][e] = sum_i K[i][d]*V[i][e], ksum[d]
// 256 threads, 4x4 register tile (round-5 configuration: 22.6us)
// ---------------------------------------------------------------------------
__global__ __launch_bounds__(256)
void chunk_stats_kernel()
{
    __shared__ float sK[CHK * DHd];
    __shared__ float sV[CHK * DHd];
    const int g = blockIdx.x, c = blockIdx.y;
    const int tid = threadIdx.x;
    const float* Kg = g_k + ((size_t)g * Tt + c * CHK) * DHd;
    const float* Vg = g_v + ((size_t)g * Tt + c * CHK) * DHd;

    for (int i = tid; i < CHK * DHd / 4; i += 256) {
        ((float4*)sK)[i] = ((const float4*)Kg)[i];
        ((float4*)sV)[i] = ((const float4*)Vg)[i];
    }
    __syncthreads();

    const int tx = tid & 15, ty = tid >> 4;
    const int d0 = ty * 4, e0 = tx * 4;
    float acc[4][4];
    #pragma unroll
    for (int u = 0; u < 4; u++)
        #pragma unroll
        for (int v = 0; v < 4; v++) acc[u][v] = 0.f;

    for (int i = 0; i < CHK; i++) {
        float4 a = *(const float4*)&sK[i * DHd + d0];
        float4 b = *(const float4*)&sV[i * DHd + e0];
        float ar[4] = {a.x, a.y, a.z, a.w};
        float br[4] = {b.x, b.y, b.z, b.w};
        #pragma unroll
        for (int u = 0; u < 4; u++)
            #pragma unroll
            for (int v = 0; v < 4; v++)
                acc[u][v] = fmaf(ar[u], br[v], acc[u][v]);
    }

    float* outp = g_state + ((size_t)g * NCk + c) * DHd * DHd;
    #pragma unroll
    for (int u = 0; u < 4; u++)
        *(float4*)&outp[(d0 + u) * DHd + e0] =
            make_float4(acc[u][0], acc[u][1], acc[u][2], acc[u][3]);

    if (tid < DHd) {
        float s = 0.f;
        for (int i = 0; i < CHK; i++) s += sK[i * DHd + tid];
        g_zsum[((size_t)g * NCk + c) * DHd + tid] = s;
    }
}

// ---------------------------------------------------------------------------
// Pass 2: exclusive prefix over chunks (batched loads -> register scan)
// ---------------------------------------------------------------------------
__global__ void scan_state_kernel()
{
    const int g = blockIdx.x;
    const int j = blockIdx.y * 256 + threadIdx.x;   // < 4096
    float* base = g_state + (size_t)g * NCk * DHd * DHd + j;
    float r[NCk];
    #pragma unroll
    for (int c = 0; c < NCk; c++) r[c] = base[(size_t)c * DHd * DHd];
    float run = 0.f;
    #pragma unroll
    for (int c = 0; c < NCk; c++) {
        base[(size_t)c * DHd * DHd] = run;
        run += r[c];
    }
}

__global__ void scan_z_kernel()
{
    const int g = blockIdx.x;
    const int j = threadIdx.x;  // < 64
    float* base = g_zsum + (size_t)g * NCk * DHd + j;
    float r[NCk];
    #pragma unroll
    for (int c = 0; c < NCk; c++) r[c] = base[c * DHd];
    float run = 0.f;
    #pragma unroll
    for (int c = 0; c < NCk; c++) {
        base[c * DHd] = run;
        run += r[c];
    }
}

// ---------------------------------------------------------------------------
// Pass 3: per-chunk output.  out = (maskedA@V + Q@S) / max(denom, eps)
// Writes bf16 hi/lo split directly (feeds final GEMM).
// ---------------------------------------------------------------------------
__global__ __launch_bounds__(256)
void attn_out_kernel()
{
    extern __shared__ float sm[];
    float* sQ   = sm;            // 4096 (pitch 64)
    float* sKV  = sQ + 4096;     // 4160 (K pitch 65, then V pitch 64)
    float* sS   = sKV + 4160;    // 4096 (pitch 64)
    float* sA   = sS + 4096;     // 4096 (pitch 64)
    float* zrun = sA + 4096;     // 64
    float* sden = zrun + 64;     // 64

    const int g = blockIdx.x, c = blockIdx.y;
    const int tid = threadIdx.x;
    const float* Qg = g_q + ((size_t)g * Tt + c * CHK) * DHd;
    const float* Kg = g_k + ((size_t)g * Tt + c * CHK) * DHd;
    const float* Vg = g_v + ((size_t)g * Tt + c * CHK) * DHd;
    const float* Sg = g_state + ((size_t)g * NCk + c) * DHd * DHd;

    for (int i = tid; i < 1024; i += 256) {
        ((float4*)sQ)[i] = ((const float4*)Qg)[i];
        ((float4*)sS)[i] = ((const float4*)Sg)[i];
        float4 kv = ((const float4*)Kg)[i];
        int j = i * 4;
        int r = j >> 6, col = j & 63;
        float* p = sKV + r * 65 + col;
        p[0] = kv.x; p[1] = kv.y; p[2] = kv.z; p[3] = kv.w;
    }
    if (tid < DHd) zrun[tid] = g_zsum[((size_t)g * NCk + c) * DHd + tid];
    __syncthreads();

    const int tx = tid & 15, ty = tid >> 4;
    const int i0 = ty * 4, j0 = tx * 4;

    // A = (Q K^T) masked causal (inclusive)
    {
        float acc[4][4];
        #pragma unroll
        for (int u = 0; u < 4; u++)
            #pragma unroll
            for (int v = 0; v < 4; v++) acc[u][v] = 0.f;
        for (int d = 0; d < DHd; d++) {
            float a[4], b[4];
            #pragma unroll
            for (int u = 0; u < 4; u++) a[u] = sQ[(i0 + u) * 64 + d];
            #pragma unroll
            for (int v = 0; v < 4; v++) b[v] = sKV[(j0 + v) * 65 + d];
            #pragma unroll
            for (int u = 0; u < 4; u++)
                #pragma unroll
                for (int v = 0; v < 4; v++)
                    acc[u][v] = fmaf(a[u], b[v], acc[u][v]);
        }
        #pragma unroll
        for (int u = 0; u < 4; u++)
            #pragma unroll
            for (int v = 0; v < 4; v++)
                sA[(i0 + u) * 64 + j0 + v] = (j0 + v <= i0 + u) ? acc[u][v] : 0.f;
    }
    __syncthreads();

    for (int i = tid; i < 1024; i += 256)
        ((float4*)sKV)[i] = ((const float4*)Vg)[i];
    if (tid < CHK) {
        float s = 0.f;
        for (int j = 0; j < CHK; j++) s += sA[tid * 64 + j];
        for (int d = 0; d < DHd; d++) s = fmaf(sQ[tid * 64 + d], zrun[d], s);
        sden[tid] = fmaxf(s, EPSv);
    }
    __syncthreads();

    {
        const int e0 = j0;
        float acc[4][4];
        #pragma unroll
        for (int u = 0; u < 4; u++)
            #pragma unroll
            for (int v = 0; v < 4; v++) acc[u][v] = 0.f;

        for (int j = 0; j < CHK; j++) {
            float4 b4 = *(const float4*)&sKV[j * 64 + e0];
            float b[4] = {b4.x, b4.y, b4.z, b4.w};
            float a[4];
            #pragma unroll
            for (int u = 0; u < 4; u++) a[u] = sA[(i0 + u) * 64 + j];
            #pragma unroll
            for (int u = 0; u < 4; u++)
                #pragma unroll
                for (int v = 0; v < 4; v++)
                    acc[u][v] = fmaf(a[u], b[v], acc[u][v]);
        }
        for (int d = 0; d < DHd; d++) {
            float4 b4 = *(const float4*)&sS[d * 64 + e0];
            float b[4] = {b4.x, b4.y, b4.z, b4.w};
            float a[4];
            #pragma unroll
            for (int u = 0; u < 4; u++) a[u] = sQ[(i0 + u) * 64 + d];
            #pragma unroll
            for (int u = 0; u < 4; u++)
                #pragma unroll
                for (int v = 0; v < 4; v++)
                    acc[u][v] = fmaf(a[u], b[v], acc[u][v]);
        }

        const int b = g / Hh, h = g % Hh;
        #pragma unroll
        for (int u = 0; u < 4; u++) {
            int t = c * CHK + i0 + u;
            float inv = 1.f / sden[i0 + u];
            float4 o = make_float4(acc[u][0] * inv, acc[u][1] * inv,
                                   acc[u][2] * inv, acc[u][3] * inv);
            size_t idx = ((size_t)(b * Tt + t) * Hh + h) * DHd + e0;
            uint2 hi, lo;
            split_bf16x4(o, hi, lo);
            *(uint2*)&g_ahi[idx] = hi;
            *(uint2*)&g_alo[idx] = lo;
        }
    }
}

// ---------------------------------------------------------------------------
extern "C" void kernel_launch(void* const* d_in, const int* in_sizes, int n_in,
                              void* d_out, int out_size)
{
    const float* x  = (const float*)d_in[0];
    const float* Wq = (const float*)d_in[1];
    const float* bq = (const float*)d_in[2];
    const float* Wk = (const float*)d_in[3];
    const float* bk = (const float*)d_in[4];
    const float* Wv = (const float*)d_in[5];
    const float* bv = (const float*)d_in[6];
    const float* Wo = (const float*)d_in[7];
    const float* bo = (const float*)d_in[8];
    float* out = (float*)d_out;

    float *pq, *pk, *pv;
    __nv_bfloat16 *pxhi, *pxlo, *pwhi, *pwlo, *pahi, *palo;
    cudaGetSymbolAddress((void**)&pq,   g_q);
    cudaGetSymbolAddress((void**)&pk,   g_k);
    cudaGetSymbolAddress((void**)&pv,   g_v);
    cudaGetSymbolAddress((void**)&pxhi, g_xhi);
    cudaGetSymbolAddress((void**)&pxlo, g_xlo);
    cudaGetSymbolAddress((void**)&pwhi, g_whi);
    cudaGetSymbolAddress((void**)&pwlo, g_wlo);
    cudaGetSymbolAddress((void**)&pahi, g_ahi);
    cudaGetSymbolAddress((void**)&palo, g_alo);

    static int attr_done = 0;
    if (!attr_done) {
        cudaFuncSetAttribute(mma_gemm_kernel,
                             cudaFuncAttributeMaxDynamicSharedMemorySize, SMEM_GEMM);
        cudaFuncSetAttribute(attn_out_kernel,
                             cudaFuncAttributeMaxDynamicSharedMemorySize,
                             (4096 + 4160 + 4096 + 4096 + 64 + 64) * (int)sizeof(float));
        attr_done = 1;
    }
    const int smem3 = (4096 + 4160 + 4096 + 4096 + 64 + 64) * sizeof(float);

    // --- split fp32 -> bf16 hi/lo ---
    const int xN4 = Mrows * Dd / 4;       // 1M
    const int wN4 = Dd * Dd / 4;          // 256K per matrix
    split_x_kernel<<<(xN4 + 255) / 256, 256>>>((const float4*)x,
        (uint2*)pxhi, (uint2*)pxlo, xN4);
    split_w_kernel<<<(4 * wN4) / 256, 256>>>(
        (const float4*)Wq, (const float4*)Wk, (const float4*)Wv, (const float4*)Wo,
        (uint2*)pwhi, (uint2*)pwlo);

    // --- Q/K/V projections in one batched launch (tensor cores) ---
    dim3 gQKV(Mrows / 128, Dd / 256, 3);   // (32, 4, 3)
    mma_gemm_kernel<<<gQKV, 256, SMEM_GEMM>>>(pxhi, pxlo, pwhi, pwlo,
        bq, bk, bv, pq, pk, pv, 0);

    // --- linear attention ---
    chunk_stats_kernel<<<dim3(Gheads, NCk), 256>>>();
    scan_state_kernel<<<dim3(Gheads, DHd * DHd / 256), 256>>>();
    scan_z_kernel<<<Gheads, DHd>>>();
    attn_out_kernel<<<dim3(Gheads, NCk), 256, smem3>>>();

    // --- output projection ---
    dim3 gOut(Mrows / 128, Dd / 256, 1);
    mma_gemm_kernel<<<gOut, 256, SMEM_GEMM>>>(pahi, palo,
        pwhi + 3 * (size_t)Dd * Dd, pwlo + 3 * (size_t)Dd * Dd,
        bo, bo, bo, out, out, out, 2);
}

// round 8
// speedup vs baseline: 2.3731x; 1.0345x over previous
#include <cuda_runtime.h>
#include <cuda_bf16.h>
#include <cstdint>
#include <math.h>

// Problem constants
#define Bb   2
#define Tt   2048
#define Dd   1024
#define Hh   16
#define DHd  64
#define Mrows (Bb*Tt)      // 4096
#define Gheads (Bb*Hh)     // 32
#define CHK  64
#define NCk  (Tt/CHK)      // 32
#define EPSv 1e-6f

// Scratch (device globals: allocation-free per harness rules)
__device__ float g_q[Gheads*Tt*DHd];
__device__ float g_k[Gheads*Tt*DHd];
__device__ float g_v[Gheads*Tt*DHd];
__device__ float g_state[Gheads*NCk*DHd*DHd];
__device__ float g_zsum[Gheads*NCk*DHd];

// bf16 hi/lo split buffers
__device__ __align__(16) __nv_bfloat16 g_xhi[Mrows*Dd];
__device__ __align__(16) __nv_bfloat16 g_xlo[Mrows*Dd];
__device__ __align__(16) __nv_bfloat16 g_whi[4*Dd*Dd];
__device__ __align__(16) __nv_bfloat16 g_wlo[4*Dd*Dd];
__device__ __align__(16) __nv_bfloat16 g_ahi[Mrows*Dd];
__device__ __align__(16) __nv_bfloat16 g_alo[Mrows*Dd];

// ===========================================================================
// helpers
// ===========================================================================
__device__ __forceinline__ uint32_t smem_to_u32(const void* p) {
    uint32_t a;
    asm("{ .reg .u64 t; cvta.to.shared.u64 t, %1; cvt.u32.u64 %0, t; }"
        : "=r"(a) : "l"(p));
    return a;
}

__device__ __forceinline__ void cp16(uint32_t saddr, const void* g) {
    asm volatile("cp.async.cg.shared.global [%0], [%1], 16;"
                 :: "r"(saddr), "l"(g));
}
#define CP_COMMIT() asm volatile("cp.async.commit_group;" ::: "memory")
#define CP_WAIT1()  asm volatile("cp.async.wait_group 1;" ::: "memory")

#define LDSM4(r, addr) \
    asm volatile("ldmatrix.sync.aligned.m8n8.x4.shared.b16 {%0,%1,%2,%3}, [%4];" \
                 : "=r"((r)[0]), "=r"((r)[1]), "=r"((r)[2]), "=r"((r)[3]) \
                 : "r"(addr))

__device__ __forceinline__ void mma16816(float* c, const uint32_t* a, const uint32_t* b) {
    asm volatile(
        "mma.sync.aligned.m16n8k16.row.col.f32.bf16.bf16.f32 "
        "{%0,%1,%2,%3}, {%4,%5,%6,%7}, {%8,%9}, {%0,%1,%2,%3};"
        : "+f"(c[0]), "+f"(c[1]), "+f"(c[2]), "+f"(c[3])
        : "r"(a[0]), "r"(a[1]), "r"(a[2]), "r"(a[3]), "r"(b[0]), "r"(b[1]));
}

// fp32 float4 -> packed hi/lo bf16 (4 each, as uint2)
__device__ __forceinline__ void split_bf16x4(float4 a, uint2& hi, uint2& lo)
{
    __nv_bfloat16 h0 = __float2bfloat16(a.x);
    __nv_bfloat16 h1 = __float2bfloat16(a.y);
    __nv_bfloat16 h2 = __float2bfloat16(a.z);
    __nv_bfloat16 h3 = __float2bfloat16(a.w);
    __nv_bfloat16 l0 = __float2bfloat16(a.x - __bfloat162float(h0));
    __nv_bfloat16 l1 = __float2bfloat16(a.y - __bfloat162float(h1));
    __nv_bfloat16 l2 = __float2bfloat16(a.z - __bfloat162float(h2));
    __nv_bfloat16 l3 = __float2bfloat16(a.w - __bfloat162float(h3));
    hi.x = (uint32_t)__bfloat16_as_ushort(h0) | ((uint32_t)__bfloat16_as_ushort(h1) << 16);
    hi.y = (uint32_t)__bfloat16_as_ushort(h2) | ((uint32_t)__bfloat16_as_ushort(h3) << 16);
    lo.x = (uint32_t)__bfloat16_as_ushort(l0) | ((uint32_t)__bfloat16_as_ushort(l1) << 16);
    lo.y = (uint32_t)__bfloat16_as_ushort(l2) | ((uint32_t)__bfloat16_as_ushort(l3) << 16);
}

// ===========================================================================
// split kernels: fp32 -> bf16 hi/lo
// ===========================================================================
__global__ void split_x_kernel(const float4* __restrict__ src,
                               uint2* __restrict__ hi, uint2* __restrict__ lo, int n4)
{
    int i = blockIdx.x * blockDim.x + threadIdx.x;
    if (i >= n4) return;
    float4 v = __ldg(&src[i]);
    uint2 h, l;
    split_bf16x4(v, h, l);
    hi[i] = h;
    lo[i] = l;
}

// all 4 weight matrices in one launch; quarter = i >> 18 (Dd*Dd/4 = 2^18)
__global__ void split_w_kernel(const float4* __restrict__ w0,
                               const float4* __restrict__ w1,
                               const float4* __restrict__ w2,
                               const float4* __restrict__ w3,
                               uint2* __restrict__ hi, uint2* __restrict__ lo)
{
    int i = blockIdx.x * blockDim.x + threadIdx.x;
    const int quarter = i >> 18;
    const int r = i & ((1 << 18) - 1);
    const float4* src = (quarter == 0) ? w0 : (quarter == 1) ? w1
                       : (quarter == 2) ? w2 : w3;
    float4 v = __ldg(&src[r]);
    uint2 h, l;
    split_bf16x4(v, h, l);
    hi[i] = h;
    lo[i] = l;
}

// Diagnostic placeholder: shifts the QKV GEMM into the ncu capture slot (#4).
__global__ void nop_kernel() {}

// ===========================================================================
// Tensor-core GEMM via mma.sync (bf16x3 split):
// C[M=4096,N=1024] = A[M,K=1024] @ W[N,K]^T + bias
// CTA tile 128x256, warp tile 64x64, BK=32, 3-stage cp.async.
// ===========================================================================
#define BKc   32                 // bf16 K per chunk
#define NCH   (Dd/BKc)           // 32
#define SSTR  40                 // smem row stride (bf16): 32 data + 8 pad
#define A_SMB (128*SSTR*2)       // 10240 B
#define W_SMB (256*SSTR*2)       // 20480 B
#define STAGE_SMB (2*A_SMB + 2*W_SMB)  // 61440 B
#define NSTAGE 3
#define SMEM_GEMM (NSTAGE*STAGE_SMB)   // 184320 B

__global__ __launch_bounds__(256, 1)
void mma_gemm_kernel(const __nv_bfloat16* __restrict__ Ahi,
                     const __nv_bfloat16* __restrict__ Alo,
                     const __nv_bfloat16* __restrict__ WhiB,
                     const __nv_bfloat16* __restrict__ WloB,
                     const float* __restrict__ b0,
                     const float* __restrict__ b1,
                     const float* __restrict__ b2,
                     float* __restrict__ d0,
                     float* __restrict__ d1,
                     float* __restrict__ d2,
                     int mode)
{
    extern __shared__ char smem[];
    const uint32_t sb = smem_to_u32(smem);
    const int tid  = threadIdx.x;
    const int lane = tid & 31, wid = tid >> 5;
    const int m0 = blockIdx.x * 128, n0 = blockIdx.y * 256;
    const int z  = blockIdx.z;

    const __nv_bfloat16* Whi = WhiB + (size_t)z * Dd * Dd;
    const __nv_bfloat16* Wlo = WloB + (size_t)z * Dd * Dd;
    const float* bias = (z == 0) ? b0 : (z == 1) ? b1 : b2;
    float* dst        = (z == 0) ? d0 : (z == 1) ? d1 : d2;
    const bool do_elu = (mode == 0) && (z < 2);

    // ---- loader mapping: 4 groups x 64 threads ----
    const int grp = tid >> 6;
    const int lt  = tid & 63;
    const __nv_bfloat16* gtile;
    uint32_t toff;
    if      (grp == 0) { gtile = Ahi + (size_t)m0 * Dd; toff = 0; }
    else if (grp == 1) { gtile = Alo + (size_t)m0 * Dd; toff = A_SMB; }
    else if (grp == 2) { gtile = Whi + (size_t)n0 * Dd; toff = 2*A_SMB; }
    else               { gtile = Wlo + (size_t)n0 * Dd; toff = 2*A_SMB + W_SMB; }
    const bool isW = (grp >= 2);

    float acc[4][8][4];
    #pragma unroll
    for (int a = 0; a < 4; a++)
        #pragma unroll
        for (int b = 0; b < 8; b++)
            #pragma unroll
            for (int c = 0; c < 4; c++) acc[a][b][c] = 0.f;

    // issue loads of chunk kc into stage kc%NSTAGE
    auto issue = [&](int kc) {
        const uint32_t stb = sb + (kc % NSTAGE) * STAGE_SMB + toff;
        const __nv_bfloat16* g = gtile + kc * BKc;
        #pragma unroll
        for (int j = 0; j < 16; j++) {
            if (j < 8 || isW) {
                int chunk = lt + j * 64;       // A: 0..511, W: 0..1023
                int row = chunk >> 2;
                int c8  = (chunk & 3) * 8;
                cp16(stb + (uint32_t)(row * SSTR + c8) * 2,
                     g + (size_t)row * Dd + c8);
            }
        }
    };

    issue(0); CP_COMMIT();
    issue(1); CP_COMMIT();

    // warp layout: 2 (M) x 4 (N); warp tile 64x64
    const int wm = (wid & 1) * 64;
    const int wn = (wid >> 1) * 64;
    const int arow = (lane & 7) + ((lane >> 3) & 1) * 8;
    const int acol = ((lane >> 4) & 1) * 8;
    const int brow = (lane & 7) + ((lane >> 4) & 1) * 8;
    const int bcol = ((lane >> 3) & 1) * 8;

    for (int kc = 0; kc < NCH; kc++) {
        CP_WAIT1();
        __syncthreads();
        if (kc + 2 < NCH) { issue(kc + 2); CP_COMMIT(); }

        const uint32_t stb = sb + (kc % NSTAGE) * STAGE_SMB;
        const uint32_t aH = stb;
        const uint32_t aL = stb + A_SMB;
        const uint32_t wH = stb + 2 * A_SMB;
        const uint32_t wL = stb + 2 * A_SMB + W_SMB;

        #pragma unroll
        for (int ks = 0; ks < 2; ks++) {
            uint32_t ah[4][4], al[4][4];
            #pragma unroll
            for (int mi = 0; mi < 4; mi++) {
                uint32_t off = (uint32_t)((wm + mi * 16 + arow) * SSTR + ks * 16 + acol) * 2;
                LDSM4(ah[mi], aH + off);
                LDSM4(al[mi], aL + off);
            }
            #pragma unroll
            for (int nj = 0; nj < 4; nj++) {
                uint32_t bh[4], bl[4];
                uint32_t off = (uint32_t)((wn + nj * 16 + brow) * SSTR + ks * 16 + bcol) * 2;
                LDSM4(bh, wH + off);
                LDSM4(bl, wL + off);
                // pass 1: hi*hi over 8 distinct accumulators
                #pragma unroll
                for (int mi = 0; mi < 4; mi++)
                    #pragma unroll
                    for (int hf = 0; hf < 2; hf++)
                        mma16816(acc[mi][nj * 2 + hf], ah[mi], &bh[hf * 2]);
                // pass 2: hi*lo
                #pragma unroll
                for (int mi = 0; mi < 4; mi++)
                    #pragma unroll
                    for (int hf = 0; hf < 2; hf++)
                        mma16816(acc[mi][nj * 2 + hf], ah[mi], &bl[hf * 2]);
                // pass 3: lo*hi
                #pragma unroll
                for (int mi = 0; mi < 4; mi++)
                    #pragma unroll
                    for (int hf = 0; hf < 2; hf++)
                        mma16816(acc[mi][nj * 2 + hf], al[mi], &bh[hf * 2]);
            }
        }
    }

    // ---- epilogue ----
    const int gid = lane >> 2, qid = lane & 3;
    float bv[16];
    #pragma unroll
    for (int ni = 0; ni < 8; ni++) {
        int n = n0 + wn + ni * 8 + qid * 2;
        bv[2 * ni]     = __ldg(&bias[n]);
        bv[2 * ni + 1] = __ldg(&bias[n + 1]);
    }

    #pragma unroll
    for (int mi = 0; mi < 4; mi++) {
        #pragma unroll
        for (int rr = 0; rr < 2; rr++) {
            const int m = m0 + wm + mi * 16 + gid + rr * 8;
            #pragma unroll
            for (int ni = 0; ni < 8; ni++) {
                const int n = n0 + wn + ni * 8 + qid * 2;
                float v0 = acc[mi][ni][rr * 2 + 0] + bv[2 * ni];
                float v1 = acc[mi][ni][rr * 2 + 1] + bv[2 * ni + 1];
                if (do_elu) {
                    v0 = (v0 > 0.f) ? (v0 + 1.f) : __expf(v0);
                    v1 = (v1 > 0.f) ? (v1 + 1.f) : __expf(v1);
                }
                if (mode == 2) {
                    *(float2*)&dst[(size_t)m * Dd + n] = make_float2(v0, v1);
                } else {
                    const int h = n >> 6, dh = n & 63;
                    const int b = m >> 11, t = m & (Tt - 1);
                    *(float2*)&dst[((size_t)(b * Hh + h) * Tt + t) * DHd + dh] =
                        make_float2(v0, v1);
                }
            }
        }
    }
}

// ---------------------------------------------------------------------------
// Pass 1: per-chunk local stats  KtV[d][e] = sum_i K[i][d]*V[i][e], ksum[d]
// 128 threads, 8x4 register tile (0.67 FMA/byte)
// ---------------------------------------------------------------------------
__global__ __launch_bounds__(128)
void chunk_stats_kernel()
{
    __shared__ float sK[CHK * DHd];
    __shared__ float sV[CHK * DHd];
    const int g = blockIdx.x, c = blockIdx.y;
    const int tid = threadIdx.x;
    const float* Kg = g_k + ((size_t)g * Tt + c * CHK) * DHd;
    const float* Vg = g_v + ((size_t)g * Tt + c * CHK) * DHd;

    for (int i = tid; i < CHK * DHd / 4; i += 128) {
        ((float4*)sK)[i] = ((const float4*)Kg)[i];
        ((float4*)sV)[i] = ((const float4*)Vg)[i];
    }
    __syncthreads();

    const int tx = tid & 15, ty = tid >> 4;   // 16 x 8
    const int d0 = ty * 8, e0 = tx * 4;
    float acc[8][4];
    #pragma unroll
    for (int u = 0; u < 8; u++)
        #pragma unroll
        for (int v = 0; v < 4; v++) acc[u][v] = 0.f;

    for (int i = 0; i < CHK; i++) {
        float a[8], b[4];
        *(float4*)(a)     = *(const float4*)&sK[i * DHd + d0];
        *(float4*)(a + 4) = *(const float4*)&sK[i * DHd + d0 + 4];
        *(float4*)(b)     = *(const float4*)&sV[i * DHd + e0];
        #pragma unroll
        for (int u = 0; u < 8; u++)
            #pragma unroll
            for (int v = 0; v < 4; v++)
                acc[u][v] = fmaf(a[u], b[v], acc[u][v]);
    }

    float* outp = g_state + ((size_t)g * NCk + c) * DHd * DHd;
    #pragma unroll
    for (int u = 0; u < 8; u++)
        *(float4*)&outp[(d0 + u) * DHd + e0] =
            make_float4(acc[u][0], acc[u][1], acc[u][2], acc[u][3]);

    if (tid < DHd) {
        float s = 0.f;
        for (int i = 0; i < CHK; i++) s += sK[i * DHd + tid];
        g_zsum[((size_t)g * NCk + c) * DHd + tid] = s;
    }
}

// ---------------------------------------------------------------------------
// Pass 2: exclusive prefix over chunks (batched loads -> register scan)
// ---------------------------------------------------------------------------
__global__ void scan_state_kernel()
{
    const int g = blockIdx.x;
    const int j = blockIdx.y * 256 + threadIdx.x;   // < 4096
    float* base = g_state + (size_t)g * NCk * DHd * DHd + j;
    float r[NCk];
    #pragma unroll
    for (int c = 0; c < NCk; c++) r[c] = base[(size_t)c * DHd * DHd];
    float run = 0.f;
    #pragma unroll
    for (int c = 0; c < NCk; c++) {
        base[(size_t)c * DHd * DHd] = run;
        run += r[c];
    }
}

__global__ void scan_z_kernel()
{
    const int g = blockIdx.x;
    const int j = threadIdx.x;  // < 64
    float* base = g_zsum + (size_t)g * NCk * DHd + j;
    float r[NCk];
    #pragma unroll
    for (int c = 0; c < NCk; c++) r[c] = base[c * DHd];
    float run = 0.f;
    #pragma unroll
    for (int c = 0; c < NCk; c++) {
        base[c * DHd] = run;
        run += r[c];
    }
}

// ---------------------------------------------------------------------------
// Pass 3: per-chunk output.  out = (maskedA@V + Q@S) / max(denom, eps)
// Writes bf16 hi/lo split directly (feeds final GEMM).
// ---------------------------------------------------------------------------
__global__ __launch_bounds__(256)
void attn_out_kernel()
{
    extern __shared__ float sm[];
    float* sQ   = sm;            // 4096 (pitch 64)
    float* sKV  = sQ + 4096;     // 4160 (K pitch 65, then V pitch 64)
    float* sS   = sKV + 4160;    // 4096 (pitch 64)
    float* sA   = sS + 4096;     // 4096 (pitch 64)
    float* zrun = sA + 4096;     // 64
    float* sden = zrun + 64;     // 64

    const int g = blockIdx.x, c = blockIdx.y;
    const int tid = threadIdx.x;
    const float* Qg = g_q + ((size_t)g * Tt + c * CHK) * DHd;
    const float* Kg = g_k + ((size_t)g * Tt + c * CHK) * DHd;
    const float* Vg = g_v + ((size_t)g * Tt + c * CHK) * DHd;
    const float* Sg = g_state + ((size_t)g * NCk + c) * DHd * DHd;

    for (int i = tid; i < 1024; i += 256) {
        ((float4*)sQ)[i] = ((const float4*)Qg)[i];
        ((float4*)sS)[i] = ((const float4*)Sg)[i];
        float4 kv = ((const float4*)Kg)[i];
        int j = i * 4;
        int r = j >> 6, col = j & 63;
        float* p = sKV + r * 65 + col;
        p[0] = kv.x; p[1] = kv.y; p[2] = kv.z; p[3] = kv.w;
    }
    if (tid < DHd) zrun[tid] = g_zsum[((size_t)g * NCk + c) * DHd + tid];
    __syncthreads();

    const int tx = tid & 15, ty = tid >> 4;
    const int i0 = ty * 4, j0 = tx * 4;

    // A = (Q K^T) masked causal (inclusive)
    {
        float acc[4][4];
        #pragma unroll
        for (int u = 0; u < 4; u++)
            #pragma unroll
            for (int v = 0; v < 4; v++) acc[u][v] = 0.f;
        for (int d = 0; d < DHd; d++) {
            float a[4], b[4];
            #pragma unroll
            for (int u = 0; u < 4; u++) a[u] = sQ[(i0 + u) * 64 + d];
            #pragma unroll
            for (int v = 0; v < 4; v++) b[v] = sKV[(j0 + v) * 65 + d];
            #pragma unroll
            for (int u = 0; u < 4; u++)
                #pragma unroll
                for (int v = 0; v < 4; v++)
                    acc[u][v] = fmaf(a[u], b[v], acc[u][v]);
        }
        #pragma unroll
        for (int u = 0; u < 4; u++)
            #pragma unroll
            for (int v = 0; v < 4; v++)
                sA[(i0 + u) * 64 + j0 + v] = (j0 + v <= i0 + u) ? acc[u][v] : 0.f;
    }
    __syncthreads();

    for (int i = tid; i < 1024; i += 256)
        ((float4*)sKV)[i] = ((const float4*)Vg)[i];
    if (tid < CHK) {
        float s = 0.f;
        for (int j = 0; j < CHK; j++) s += sA[tid * 64 + j];
        for (int d = 0; d < DHd; d++) s = fmaf(sQ[tid * 64 + d], zrun[d], s);
        sden[tid] = fmaxf(s, EPSv);
    }
    __syncthreads();

    {
        const int e0 = j0;
        float acc[4][4];
        #pragma unroll
        for (int u = 0; u < 4; u++)
            #pragma unroll
            for (int v = 0; v < 4; v++) acc[u][v] = 0.f;

        for (int j = 0; j < CHK; j++) {
            float4 b4 = *(const float4*)&sKV[j * 64 + e0];
            float b[4] = {b4.x, b4.y, b4.z, b4.w};
            float a[4];
            #pragma unroll
            for (int u = 0; u < 4; u++) a[u] = sA[(i0 + u) * 64 + j];
            #pragma unroll
            for (int u = 0; u < 4; u++)
                #pragma unroll
                for (int v = 0; v < 4; v++)
                    acc[u][v] = fmaf(a[u], b[v], acc[u][v]);
        }
        for (int d = 0; d < DHd; d++) {
            float4 b4 = *(const float4*)&sS[d * 64 + e0];
            float b[4] = {b4.x, b4.y, b4.z, b4.w};
            float a[4];
            #pragma unroll
            for (int u = 0; u < 4; u++) a[u] = sQ[(i0 + u) * 64 + d];
            #pragma unroll
            for (int u = 0; u < 4; u++)
                #pragma unroll
                for (int v = 0; v < 4; v++)
                    acc[u][v] = fmaf(a[u], b[v], acc[u][v]);
        }

        const int b = g / Hh, h = g % Hh;
        #pragma unroll
        for (int u = 0; u < 4; u++) {
            int t = c * CHK + i0 + u;
            float inv = 1.f / sden[i0 + u];
            float4 o = make_float4(acc[u][0] * inv, acc[u][1] * inv,
                                   acc[u][2] * inv, acc[u][3] * inv);
            size_t idx = ((size_t)(b * Tt + t) * Hh + h) * DHd + e0;
            uint2 hi, lo;
            split_bf16x4(o, hi, lo);
            *(uint2*)&g_ahi[idx] = hi;
            *(uint2*)&g_alo[idx] = lo;
        }
    }
}

// ---------------------------------------------------------------------------
extern "C" void kernel_launch(void* const* d_in, const int* in_sizes, int n_in,
                              void* d_out, int out_size)
{
    const float* x  = (const float*)d_in[0];
    const float* Wq = (const float*)d_in[1];
    const float* bq = (const float*)d_in[2];
    const float* Wk = (const float*)d_in[3];
    const float* bk = (const float*)d_in[4];
    const float* Wv = (const float*)d_in[5];
    const float* bv = (const float*)d_in[6];
    const float* Wo = (const float*)d_in[7];
    const float* bo = (const float*)d_in[8];
    float* out = (float*)d_out;

    float *pq, *pk, *pv;
    __nv_bfloat16 *pxhi, *pxlo, *pwhi, *pwlo, *pahi, *palo;
    cudaGetSymbolAddress((void**)&pq,   g_q);
    cudaGetSymbolAddress((void**)&pk,   g_k);
    cudaGetSymbolAddress((void**)&pv,   g_v);
    cudaGetSymbolAddress((void**)&pxhi, g_xhi);
    cudaGetSymbolAddress((void**)&pxlo, g_xlo);
    cudaGetSymbolAddress((void**)&pwhi, g_whi);
    cudaGetSymbolAddress((void**)&pwlo, g_wlo);
    cudaGetSymbolAddress((void**)&pahi, g_ahi);
    cudaGetSymbolAddress((void**)&palo, g_alo);

    static int attr_done = 0;
    if (!attr_done) {
        cudaFuncSetAttribute(mma_gemm_kernel,
                             cudaFuncAttributeMaxDynamicSharedMemorySize, SMEM_GEMM);
        cudaFuncSetAttribute(attn_out_kernel,
                             cudaFuncAttributeMaxDynamicSharedMemorySize,
                             (4096 + 4160 + 4096 + 4096 + 64 + 64) * (int)sizeof(float));
        attr_done = 1;
    }
    const int smem3 = (4096 + 4160 + 4096 + 4096 + 64 + 64) * sizeof(float);

    // --- split fp32 -> bf16 hi/lo ---
    const int xN4 = Mrows * Dd / 4;       // 1M
    const int wN4 = Dd * Dd / 4;          // 256K per matrix
    split_x_kernel<<<(xN4 + 255) / 256, 256>>>((const float4*)x,
        (uint2*)pxhi, (uint2*)pxlo, xN4);
    split_w_kernel<<<(4 * wN4) / 256, 256>>>(
        (const float4*)Wq, (const float4*)Wk, (const float4*)Wv, (const float4*)Wo,
        (uint2*)pwhi, (uint2*)pwlo);

    // diagnostic: shift QKV GEMM into ncu capture slot (#4)
    nop_kernel<<<1, 32>>>();

    // --- Q/K/V projections in one batched launch (tensor cores) ---
    dim3 gQKV(Mrows / 128, Dd / 256, 3);   // (32, 4, 3)
    mma_gemm_kernel<<<gQKV, 256, SMEM_GEMM>>>(pxhi, pxlo, pwhi, pwlo,
        bq, bk, bv, pq, pk, pv, 0);

    // --- linear attention ---
    chunk_stats_kernel<<<dim3(Gheads, NCk), 128>>>();
    scan_state_kernel<<<dim3(Gheads, DHd * DHd / 256), 256>>>();
    scan_z_kernel<<<Gheads, DHd>>>();
    attn_out_kernel<<<dim3(Gheads, NCk), 256, smem3>>>();

    // --- output projection ---
    dim3 gOut(Mrows / 128, Dd / 256, 1);
    mma_gemm_kernel<<<gOut, 256, SMEM_GEMM>>>(pahi, palo,
        pwhi + 3 * (size_t)Dd * Dd, pwlo + 3 * (size_t)Dd * Dd,
        bo, bo, bo, out, out, out, 2);
}